// round 4
// baseline (speedup 1.0000x reference)
#include <cuda_runtime.h>
#include <cuda_bf16.h>
#include <math.h>

#define BATCH   32
#define DIM     4096
#define NKV     8
#define REP     4
#define HD      128
#define QKVN    6144      // (32 + 2*8) * 128
#define CL      2176      // cache length
#define NCH     17        // 17 * 128 = 2176
#define KSPLIT_QKV  16
#define KSPLIT_WO   32

// ---------------- f32x2 packed-math helpers -----------------------------------
#define FFMA2(d, a, b, c) \
    asm("fma.rn.f32x2 %0, %1, %2, %3;" : "=l"(d) : "l"(a), "l"(b), "l"(c))
#define PACK2(d, s) \
    asm("mov.b64 %0, {%1, %1};" : "=l"(d) : "f"(s))
#define UNPACK2(lo, hi, v) \
    asm("mov.b64 {%0, %1}, %2;" : "=f"(lo), "=f"(hi) : "l"(v))
#define LDSV2(p01, p23, addr) \
    asm("ld.shared.v2.u64 {%0, %1}, [%2];" : "=l"(p01), "=l"(p23) : "r"(addr))

// ---------------- scratch (static device globals; no allocs allowed) ----------
__device__ float g_cos[64];
__device__ float g_sin[64];
__device__ float g_qkvp[KSPLIT_QKV * BATCH * QKVN];       // 12.6 MB
__device__ float g_q[BATCH * DIM];                        // (b, g, r, d)
__device__ float g_k[BATCH * NKV * HD];
__device__ float g_v[BATCH * NKV * HD];
__device__ float g_pacc[(size_t)BATCH * NKV * NCH * REP * HD];
__device__ float g_pm[BATCH * NKV * NCH * REP];
__device__ float g_pl[BATCH * NKV * NCH * REP];
__device__ float g_attn[BATCH * DIM];
__device__ float g_wop[KSPLIT_WO * BATCH * DIM];          // 16.8 MB

// ---------------- RoPE table (double precision, tiny) -------------------------
__global__ void k_rope_table(const int* __restrict__ spp) {
    int i = threadIdx.x;
    if (i < 64) {
        int sp = *spp;
        double e    = (2.0 * (double)i) / 128.0;
        double invf = pow(10000.0, -e);
        double ang  = (double)sp * invf;
        g_cos[i] = (float)cos(ang);
        g_sin[i] = (float)sin(ang);
    }
}

// ---------------- skinny GEMM with f32x2 packed FMA ----------------------------
// out[32, N] partials over K-splits. grid(N/256, NSPLIT), 256 threads.
// Thread owns column n; 32 batch rows as 16 packed f32x2 accumulators.
// x staged TRANSPOSED in smem: xs_t[k][m], row stride 34 floats so that the
// (m, m+1) pair at one k is one aligned 8-byte broadcast LDS.64.
template<int N, int KC, bool WO>
__global__ __launch_bounds__(256) void k_gemm(const float* __restrict__ xsrc,
                                              const float* __restrict__ w) {
    __shared__ float xs_t[KC * 34];
    const int t  = threadIdx.x;
    const int k0 = blockIdx.y * KC;

    const float* xbase = WO ? (const float*)g_attn : xsrc;
    float*       obase = WO ? (float*)g_wop : (float*)g_qkvp;

    // load + transpose x chunk: [32][KC] -> xs_t[k][m]
    const float4* xg = (const float4*)xbase;
    const int tot4 = 32 * KC / 4;
    for (int j = t; j < tot4; j += 256) {
        int m  = j / (KC / 4);
        int c4 = j % (KC / 4);
        float4 v = xg[m * (DIM / 4) + (k0 >> 2) + c4];
        xs_t[(4 * c4 + 0) * 34 + m] = v.x;
        xs_t[(4 * c4 + 1) * 34 + m] = v.y;
        xs_t[(4 * c4 + 2) * 34 + m] = v.z;
        xs_t[(4 * c4 + 3) * 34 + m] = v.w;
    }
    __syncthreads();

    const int n = blockIdx.x * 256 + t;
    const float* wp = w + (size_t)k0 * N + n;

    unsigned long long acc[16];
    #pragma unroll
    for (int mp = 0; mp < 16; mp++) acc[mp] = 0ull;

    float wb[4];
    #pragma unroll
    for (int i = 0; i < 4; i++) wb[i] = wp[(size_t)i * N];

    for (int kb = 0; kb < KC; kb += 4) {
        float wn[4] = {0.f, 0.f, 0.f, 0.f};
        if (kb + 4 < KC) {
            #pragma unroll
            for (int i = 0; i < 4; i++) wn[i] = wp[(size_t)(kb + 4 + i) * N];
        }
        #pragma unroll
        for (int i = 0; i < 4; i++) {
            unsigned long long wpair;
            PACK2(wpair, wb[i]);
            const unsigned long long* xp =
                (const unsigned long long*)&xs_t[(kb + i) * 34];
            #pragma unroll
            for (int mp = 0; mp < 16; mp++)
                FFMA2(acc[mp], xp[mp], wpair, acc[mp]);
        }
        #pragma unroll
        for (int i = 0; i < 4; i++) wb[i] = wn[i];
    }

    float* o = obase + (size_t)blockIdx.y * 32 * N + n;
    #pragma unroll
    for (int mp = 0; mp < 16; mp++) {
        float lo, hi;
        UNPACK2(lo, hi, acc[mp]);
        o[(size_t)(2 * mp) * N]     = lo;
        o[(size_t)(2 * mp + 1) * N] = hi;
    }
}

// ---------------- reduce QKV K-split partials + RoPE ---------------------------
__global__ __launch_bounds__(256) void k_reduce_rope() {
    int idx = blockIdx.x * 256 + threadIdx.x;            // < 32*6144
    int m = idx / QKVN;
    int n = idx % QKVN;

    float s = 0.f;
    #pragma unroll
    for (int p = 0; p < KSPLIT_QKV; p++) s += g_qkvp[((size_t)p * BATCH + m) * QKVN + n];

    if (n < 5120) {                                      // q or k: apply RoPE
        int d  = n & 127;
        int n2 = (d < 64) ? n + 64 : n - 64;
        float s2 = 0.f;
        #pragma unroll
        for (int p = 0; p < KSPLIT_QKV; p++) s2 += g_qkvp[((size_t)p * BATCH + m) * QKVN + n2];
        int i = d & 63;
        float out = (d < 64) ? s * g_cos[i] - s2 * g_sin[i]
                             : s * g_cos[i] + s2 * g_sin[i];
        if (n < 4096) g_q[m * DIM + n] = out;
        else          g_k[m * (NKV * HD) + (n - 4096)] = out;
    } else {
        g_v[m * (NKV * HD) + (n - 5120)] = s;
    }
}

// ---------------- flash-decode attention v2 ------------------------------------
// grid (NCH, 256), 128 threads. One 128-row tile in dynamic smem (XOR-swizzled),
// reused for K then V. All threads compute in both phases; f32x2 FMA over the
// 4 head-reps. V-tile loads are issued before the softmax to overlap latency.
__global__ __launch_bounds__(128) void k_attn2(const float* __restrict__ ck,
                                               const float* __restrict__ cv,
                                               const int* __restrict__ spp) {
    extern __shared__ float sm[];
    float* kvs = sm;              // 16384 floats (64 KB), swizzled tile
    float* qp  = sm + 16384;      // 512: q packed [d][4 reps]
    float* ps  = sm + 16896;      // 512: scores/probs transposed [s][4 reps]
    float* red = sm + 17408;      // 8: m[0..3], l[4..7]

    const int t  = threadIdx.x;
    const int c  = blockIdx.x;
    const int bg = blockIdx.y;
    const int sp = *spp;
    const float SCALE = 0.08838834764831845f;            // 1/sqrt(128)

    float4* kv4 = (float4*)kvs;
    const float4* ck4 = (const float4*)ck;
    const float4* cv4 = (const float4*)cv;
    const float4* gk4 = (const float4*)g_k;
    const float4* gv4 = (const float4*)g_v;

    // q packed: qp[d*4 + r]
    #pragma unroll
    for (int it = 0; it < 4; it++) {
        int idx = t + 128 * it;
        int d = idx & 127, r = idx >> 7;
        qp[d * 4 + r] = g_q[(size_t)bg * 512 + r * 128 + d];
    }

    // ---- K tile: 128 rows x 128 floats, swizzle c4 ^= (row & 31) ----
    #pragma unroll
    for (int it = 0; it < 32; it++) {
        int j   = t + 128 * it;
        int row = j >> 5, c4 = j & 31;
        int s   = c * 128 + row;
        float4 v = (s == sp) ? gk4[bg * 32 + c4]
                             : ck4[((size_t)bg * CL + s) * 32 + c4];
        kv4[row * 32 + (c4 ^ (row & 31))] = v;
    }
    __syncthreads();

    // ---- scores: thread t owns row t, 4 reps as 2 packed accumulators ----
    {
        unsigned long long a01 = 0ull, a23 = 0ull;
        const int base4 = t * 32;
        const int sw    = t & 31;
        unsigned qa = (unsigned)__cvta_generic_to_shared(qp);
        #pragma unroll
        for (int d4 = 0; d4 < 32; d4++) {
            float4 kvv = kv4[base4 + (d4 ^ sw)];
            unsigned qd = qa + d4 * 64;                  // 16 floats per d4
            float kd0 = kvv.x, kd1 = kvv.y, kd2 = kvv.z, kd3 = kvv.w;
            unsigned long long kp, q01, q23;
            PACK2(kp, kd0); LDSV2(q01, q23, qd +  0);
            FFMA2(a01, kp, q01, a01); FFMA2(a23, kp, q23, a23);
            PACK2(kp, kd1); LDSV2(q01, q23, qd + 16);
            FFMA2(a01, kp, q01, a01); FFMA2(a23, kp, q23, a23);
            PACK2(kp, kd2); LDSV2(q01, q23, qd + 32);
            FFMA2(a01, kp, q01, a01); FFMA2(a23, kp, q23, a23);
            PACK2(kp, kd3); LDSV2(q01, q23, qd + 48);
            FFMA2(a01, kp, q01, a01); FFMA2(a23, kp, q23, a23);
        }
        float s0, s1, s2, s3;
        UNPACK2(s0, s1, a01);
        UNPACK2(s2, s3, a23);
        bool ok = (c * 128 + t) <= sp;
        float4 sv;
        sv.x = ok ? s0 * SCALE : -1e9f;
        sv.y = ok ? s1 * SCALE : -1e9f;
        sv.z = ok ? s2 * SCALE : -1e9f;
        sv.w = ok ? s3 * SCALE : -1e9f;
        ((float4*)ps)[t] = sv;
    }
    __syncthreads();

    // ---- V tile loads (issue early; overlaps softmax below) ----
    #pragma unroll
    for (int it = 0; it < 32; it++) {
        int j   = t + 128 * it;
        int row = j >> 5, c4 = j & 31;
        int s   = c * 128 + row;
        float4 v = (s == sp) ? gv4[bg * 32 + c4]
                             : cv4[((size_t)bg * CL + s) * 32 + c4];
        kv4[row * 32 + (c4 ^ (row & 31))] = v;
    }

    // ---- softmax over this chunk: warp w handles rep r = w ----
    {
        int w = t >> 5, l = t & 31;
        float v0 = ps[(l +  0) * 4 + w];
        float v1 = ps[(l + 32) * 4 + w];
        float v2 = ps[(l + 64) * 4 + w];
        float v3 = ps[(l + 96) * 4 + w];
        float mx = fmaxf(fmaxf(v0, v1), fmaxf(v2, v3));
        #pragma unroll
        for (int off = 16; off > 0; off >>= 1)
            mx = fmaxf(mx, __shfl_xor_sync(0xffffffffu, mx, off));
        float e0 = expf(v0 - mx), e1 = expf(v1 - mx);
        float e2 = expf(v2 - mx), e3 = expf(v3 - mx);
        float sum = e0 + e1 + e2 + e3;
        #pragma unroll
        for (int off = 16; off > 0; off >>= 1)
            sum += __shfl_xor_sync(0xffffffffu, sum, off);
        ps[(l +  0) * 4 + w] = e0;
        ps[(l + 32) * 4 + w] = e1;
        ps[(l + 64) * 4 + w] = e2;
        ps[(l + 96) * 4 + w] = e3;
        if (l == 0) { red[w] = mx; red[4 + w] = sum; }
    }
    __syncthreads();

    // ---- V accumulate: thread t owns head dim d = t ----
    {
        unsigned long long o01 = 0ull, o23 = 0ull;
        const int cbase = t >> 2;
        const int ci    = t & 3;
        unsigned psa = (unsigned)__cvta_generic_to_shared(ps);
        #pragma unroll 8
        for (int s = 0; s < 128; s++) {
            float vv = kvs[s * 128 + (((cbase ^ (s & 31)) << 2) | ci)];
            unsigned long long vp, p01, p23;
            PACK2(vp, vv);
            LDSV2(p01, p23, psa + s * 16);
            FFMA2(o01, vp, p01, o01);
            FFMA2(o23, vp, p23, o23);
        }
        float o0, o1, o2, o3;
        UNPACK2(o0, o1, o01);
        UNPACK2(o2, o3, o23);
        size_t pb = ((size_t)bg * NCH + c) * REP;
        g_pacc[(pb + 0) * HD + t] = o0;
        g_pacc[(pb + 1) * HD + t] = o1;
        g_pacc[(pb + 2) * HD + t] = o2;
        g_pacc[(pb + 3) * HD + t] = o3;
        if (t < REP) { g_pm[pb + t] = red[t]; g_pl[pb + t] = red[4 + t]; }
    }
}

// ---------------- combine split-S partials -------------------------------------
__global__ __launch_bounds__(128) void k_combine() {
    __shared__ float ms[NCH * REP], ls[NCH * REP];
    int bg = blockIdx.x, t = threadIdx.x;
    if (t < NCH * REP) {
        ms[t] = g_pm[bg * NCH * REP + t];
        ls[t] = g_pl[bg * NCH * REP + t];
    }
    __syncthreads();
    #pragma unroll
    for (int r = 0; r < REP; r++) {
        float M = -1e30f;
        #pragma unroll
        for (int cc = 0; cc < NCH; cc++) M = fmaxf(M, ms[cc * REP + r]);
        float L = 0.f, val = 0.f;
        for (int cc = 0; cc < NCH; cc++) {
            float wgt = expf(ms[cc * REP + r] - M);
            L   += ls[cc * REP + r] * wgt;
            val += g_pacc[(((size_t)bg * NCH + cc) * REP + r) * HD + t] * wgt;
        }
        g_attn[(size_t)bg * 512 + r * HD + t] = val / L;
    }
}

// ---------------- WO split-K reduce --------------------------------------------
__global__ __launch_bounds__(256) void k_wo_reduce(float* __restrict__ out) {
    int idx = blockIdx.x * 256 + threadIdx.x;            // < 32*4096
    float s = 0.f;
    #pragma unroll
    for (int p = 0; p < KSPLIT_WO; p++) s += g_wop[(size_t)p * BATCH * DIM + idx];
    out[idx] = s;
}

// ---------------- launch -------------------------------------------------------
extern "C" void kernel_launch(void* const* d_in, const int* in_sizes, int n_in,
                              void* d_out, int out_size) {
    const float* x    = (const float*)d_in[0];
    const float* wqkv = (const float*)d_in[1];
    const float* wo   = (const float*)d_in[2];
    const float* ck   = (const float*)d_in[3];
    const float* cv   = (const float*)d_in[4];
    const int*   sp   = (const int*)d_in[5];
    float*       out  = (float*)d_out;

    const int ATTN_SMEM = (16384 + 512 + 512 + 8) * 4;   // 69664 B
    static int attr_done = 0;
    if (!attr_done) {
        cudaFuncSetAttribute(k_attn2, cudaFuncAttributeMaxDynamicSharedMemorySize,
                             ATTN_SMEM);
        attr_done = 1;
    }

    k_rope_table<<<1, 64>>>(sp);
    k_gemm<QKVN, DIM / KSPLIT_QKV, false>
        <<<dim3(QKVN / 256, KSPLIT_QKV), 256>>>(x, wqkv);
    k_reduce_rope<<<(BATCH * QKVN) / 256, 256>>>();
    k_attn2<<<dim3(NCH, BATCH * NKV), 128, ATTN_SMEM>>>(ck, cv, sp);
    k_combine<<<BATCH * NKV, 128>>>();
    k_gemm<DIM, DIM / KSPLIT_WO, true>
        <<<dim3(DIM / 256, KSPLIT_WO), 256>>>(nullptr, wo);
    k_wo_reduce<<<(BATCH * DIM) / 256, 256>>>(out);
}

// round 5
// speedup vs baseline: 1.4293x; 1.4293x over previous
#include <cuda_runtime.h>
#include <cuda_bf16.h>
#include <math.h>

#define BATCH   32
#define DIM     4096
#define NKV     8
#define REP     4
#define HD      128
#define QKVN    6144      // (32 + 2*8) * 128
#define CL      2176      // cache length
#define NCH     17        // 17 * 128 = 2176
#define KSPLIT_QKV  16
#define KSPLIT_WO   32

// ---------------- f32x2 packed-math helpers -----------------------------------
#define FFMA2(d, a, b, c) \
    asm("fma.rn.f32x2 %0, %1, %2, %3;" : "=l"(d) : "l"(a), "l"(b), "l"(c))
#define PACK2(d, s) \
    asm("mov.b64 %0, {%1, %1};" : "=l"(d) : "f"(s))
#define UNPACK2(lo, hi, v) \
    asm("mov.b64 {%0, %1}, %2;" : "=f"(lo), "=f"(hi) : "l"(v))
#define LDSV2(p01, p23, addr) \
    asm("ld.shared.v2.u64 {%0, %1}, [%2];" : "=l"(p01), "=l"(p23) : "r"(addr))

// ---------------- cp.async helpers ---------------------------------------------
#define CP_ASYNC16(dst_s, src_g) \
    asm volatile("cp.async.cg.shared.global [%0], [%1], 16;" \
                 :: "r"(dst_s), "l"(src_g) : "memory")
#define CP_COMMIT() asm volatile("cp.async.commit_group;" ::: "memory")
#define CP_WAIT(n)  asm volatile("cp.async.wait_group %0;" :: "n"(n) : "memory")

// ---------------- scratch (static device globals; no allocs allowed) ----------
__device__ float g_cos[64];
__device__ float g_sin[64];
__device__ float g_qkvp[KSPLIT_QKV * BATCH * QKVN];       // 12.6 MB
__device__ float g_q[BATCH * DIM];                        // (b, g, r, d)
__device__ float g_k[BATCH * NKV * HD];
__device__ float g_v[BATCH * NKV * HD];
__device__ float g_pacc[(size_t)BATCH * NKV * NCH * REP * HD];
__device__ float g_pm[BATCH * NKV * NCH * REP];
__device__ float g_pl[BATCH * NKV * NCH * REP];
__device__ float g_attn[BATCH * DIM];
__device__ float g_wop[KSPLIT_WO * BATCH * DIM];          // 16.8 MB

// ---------------- RoPE table (double precision, tiny) -------------------------
__global__ void k_rope_table(const int* __restrict__ spp) {
    int i = threadIdx.x;
    if (i < 64) {
        int sp = *spp;
        double e    = (2.0 * (double)i) / 128.0;
        double invf = pow(10000.0, -e);
        double ang  = (double)sp * invf;
        g_cos[i] = (float)cos(ang);
        g_sin[i] = (float)sin(ang);
    }
}

// ---------------- skinny GEMM with f32x2 packed FMA ----------------------------
// out[32, N] partials over K-splits. grid(N/256, NSPLIT), 256 threads.
// Thread owns column n; 32 batch rows as 16 packed f32x2 accumulators.
// x staged TRANSPOSED in smem: xs_t[k][m], row stride 34 floats so that the
// (m, m+1) pair at one k is one aligned 8-byte broadcast LDS.64.
template<int N, int KC, bool WO>
__global__ __launch_bounds__(256) void k_gemm(const float* __restrict__ xsrc,
                                              const float* __restrict__ w) {
    __shared__ float xs_t[KC * 34];
    const int t  = threadIdx.x;
    const int k0 = blockIdx.y * KC;

    const float* xbase = WO ? (const float*)g_attn : xsrc;
    float*       obase = WO ? (float*)g_wop : (float*)g_qkvp;

    // load + transpose x chunk: [32][KC] -> xs_t[k][m]
    const float4* xg = (const float4*)xbase;
    const int tot4 = 32 * KC / 4;
    for (int j = t; j < tot4; j += 256) {
        int m  = j / (KC / 4);
        int c4 = j % (KC / 4);
        float4 v = xg[m * (DIM / 4) + (k0 >> 2) + c4];
        xs_t[(4 * c4 + 0) * 34 + m] = v.x;
        xs_t[(4 * c4 + 1) * 34 + m] = v.y;
        xs_t[(4 * c4 + 2) * 34 + m] = v.z;
        xs_t[(4 * c4 + 3) * 34 + m] = v.w;
    }
    __syncthreads();

    const int n = blockIdx.x * 256 + t;
    const float* wp = w + (size_t)k0 * N + n;

    unsigned long long acc[16];
    #pragma unroll
    for (int mp = 0; mp < 16; mp++) acc[mp] = 0ull;

    float wb[4];
    #pragma unroll
    for (int i = 0; i < 4; i++) wb[i] = wp[(size_t)i * N];

    for (int kb = 0; kb < KC; kb += 4) {
        float wn[4] = {0.f, 0.f, 0.f, 0.f};
        if (kb + 4 < KC) {
            #pragma unroll
            for (int i = 0; i < 4; i++) wn[i] = wp[(size_t)(kb + 4 + i) * N];
        }
        #pragma unroll
        for (int i = 0; i < 4; i++) {
            unsigned long long wpair;
            PACK2(wpair, wb[i]);
            const unsigned long long* xp =
                (const unsigned long long*)&xs_t[(kb + i) * 34];
            #pragma unroll
            for (int mp = 0; mp < 16; mp++)
                FFMA2(acc[mp], xp[mp], wpair, acc[mp]);
        }
        #pragma unroll
        for (int i = 0; i < 4; i++) wb[i] = wn[i];
    }

    float* o = obase + (size_t)blockIdx.y * 32 * N + n;
    #pragma unroll
    for (int mp = 0; mp < 16; mp++) {
        float lo, hi;
        UNPACK2(lo, hi, acc[mp]);
        o[(size_t)(2 * mp) * N]     = lo;
        o[(size_t)(2 * mp + 1) * N] = hi;
    }
}

// ---------------- reduce QKV K-split partials + RoPE ---------------------------
__global__ __launch_bounds__(256) void k_reduce_rope() {
    int idx = blockIdx.x * 256 + threadIdx.x;            // < 32*6144
    int m = idx / QKVN;
    int n = idx % QKVN;

    float s = 0.f;
    #pragma unroll
    for (int p = 0; p < KSPLIT_QKV; p++) s += g_qkvp[((size_t)p * BATCH + m) * QKVN + n];

    if (n < 5120) {                                      // q or k: apply RoPE
        int d  = n & 127;
        int n2 = (d < 64) ? n + 64 : n - 64;
        float s2 = 0.f;
        #pragma unroll
        for (int p = 0; p < KSPLIT_QKV; p++) s2 += g_qkvp[((size_t)p * BATCH + m) * QKVN + n2];
        int i = d & 63;
        float out = (d < 64) ? s * g_cos[i] - s2 * g_sin[i]
                             : s * g_cos[i] + s2 * g_sin[i];
        if (n < 4096) g_q[m * DIM + n] = out;
        else          g_k[m * (NKV * HD) + (n - 4096)] = out;
    } else {
        g_v[m * (NKV * HD) + (n - 5120)] = s;
    }
}

// ---------------- flash-decode attention v3: cp.async double-buffered ----------
// grid (NCH, 256), 128 threads. Two 64-row tiles (64x132 pad, no XOR swizzle),
// depth-2 LDGSTS pipeline: K0,K1 in flight immediately; V0/V1 issued as K
// buffers free up. Score compute: thread = row (t<64), f32x2 over 4 reps.
// PV compute: thread = head-dim column, conflict-free smem reads.
__global__ __launch_bounds__(128) void k_attn3(const float* __restrict__ ck,
                                               const float* __restrict__ cv,
                                               const int* __restrict__ spp) {
    extern __shared__ float sm[];
    float* qp   = sm;                 // 512 : q packed [d][4 reps]
    float* ps   = sm + 512;           // 512 : scores/probs [s][4 reps]
    float* red  = sm + 1024;          // 16  : m[0..3], l[4..7]
    float* bufA = sm + 1040;          // 8448 = 64*132
    float* bufB = sm + 1040 + 8448;   // 8448

    const int t  = threadIdx.x;
    const int c  = blockIdx.x;
    const int bg = blockIdx.y;
    const int sp = *spp;
    const float SCALE = 0.08838834764831845f;            // 1/sqrt(128)

    const float4* ckb = ((const float4*)ck) + (size_t)bg * CL * 32;
    const float4* cvb = ((const float4*)cv) + (size_t)bg * CL * 32;
    const float4* gk4 = ((const float4*)g_k) + bg * 32;
    const float4* gv4 = ((const float4*)g_v) + bg * 32;

    const unsigned qa   = (unsigned)__cvta_generic_to_shared(qp);
    const unsigned psa  = (unsigned)__cvta_generic_to_shared(ps);
    const unsigned bufAs = (unsigned)__cvta_generic_to_shared(bufA);
    const unsigned bufBs = (unsigned)__cvta_generic_to_shared(bufB);

    const int s0   = c * 128;
    const int row0 = t >> 5;          // this thread copies rows row0, row0+4, ...
    const int c4t  = t & 31;

    // ---- issue K0 -> bufA, K1 -> bufB (two groups, both in flight) ----
    #pragma unroll
    for (int it = 0; it < 16; it++) {
        int row = row0 + 4 * it;
        CP_ASYNC16(bufAs + row * 528 + c4t * 16,
                   (const void*)&ckb[(s0 + row) * 32 + c4t]);
    }
    CP_COMMIT();
    #pragma unroll
    for (int it = 0; it < 16; it++) {
        int row = row0 + 4 * it;
        CP_ASYNC16(bufBs + row * 528 + c4t * 16,
                   (const void*)&ckb[(s0 + 64 + row) * 32 + c4t]);
    }
    CP_COMMIT();

    // q packed: qp[d*4 + r]  (covered by barrier after first wait)
    #pragma unroll
    for (int it = 0; it < 4; it++) {
        int idx = t + 128 * it;
        int d = idx & 127, r = idx >> 7;
        qp[d * 4 + r] = g_q[(size_t)bg * 512 + r * 128 + d];
    }

    // ================= score tile 0 =================
    CP_WAIT(1);
    __syncthreads();
    if (t < 64) {
        int sg = s0 + t;
        unsigned long long a01 = 0ull, a23 = 0ull;
        const float4* kr = (sg == sp) ? gk4 : ((const float4*)bufA) + t * 33;
        #pragma unroll 8
        for (int d4 = 0; d4 < 32; d4++) {
            float4 kv = kr[d4];
            unsigned qd = qa + d4 * 64;
            unsigned long long kp, q01, q23;
            PACK2(kp, kv.x); LDSV2(q01, q23, qd +  0);
            FFMA2(a01, kp, q01, a01); FFMA2(a23, kp, q23, a23);
            PACK2(kp, kv.y); LDSV2(q01, q23, qd + 16);
            FFMA2(a01, kp, q01, a01); FFMA2(a23, kp, q23, a23);
            PACK2(kp, kv.z); LDSV2(q01, q23, qd + 32);
            FFMA2(a01, kp, q01, a01); FFMA2(a23, kp, q23, a23);
            PACK2(kp, kv.w); LDSV2(q01, q23, qd + 48);
            FFMA2(a01, kp, q01, a01); FFMA2(a23, kp, q23, a23);
        }
        float v0, v1, v2, v3;
        UNPACK2(v0, v1, a01); UNPACK2(v2, v3, a23);
        bool ok = (sg <= sp);
        float4 sv;
        sv.x = ok ? v0 * SCALE : -1e9f;
        sv.y = ok ? v1 * SCALE : -1e9f;
        sv.z = ok ? v2 * SCALE : -1e9f;
        sv.w = ok ? v3 * SCALE : -1e9f;
        ((float4*)ps)[t] = sv;
    }
    __syncthreads();                 // all reads of bufA done; scores0 visible

    // ---- issue V0 -> bufA ----
    #pragma unroll
    for (int it = 0; it < 16; it++) {
        int row = row0 + 4 * it;
        CP_ASYNC16(bufAs + row * 528 + c4t * 16,
                   (const void*)&cvb[(s0 + row) * 32 + c4t]);
    }
    CP_COMMIT();

    // ================= score tile 1 =================
    CP_WAIT(1);                      // K1 done (V0 may still be pending)
    __syncthreads();
    if (t < 64) {
        int sg = s0 + 64 + t;
        unsigned long long a01 = 0ull, a23 = 0ull;
        const float4* kr = (sg == sp) ? gk4 : ((const float4*)bufB) + t * 33;
        #pragma unroll 8
        for (int d4 = 0; d4 < 32; d4++) {
            float4 kv = kr[d4];
            unsigned qd = qa + d4 * 64;
            unsigned long long kp, q01, q23;
            PACK2(kp, kv.x); LDSV2(q01, q23, qd +  0);
            FFMA2(a01, kp, q01, a01); FFMA2(a23, kp, q23, a23);
            PACK2(kp, kv.y); LDSV2(q01, q23, qd + 16);
            FFMA2(a01, kp, q01, a01); FFMA2(a23, kp, q23, a23);
            PACK2(kp, kv.z); LDSV2(q01, q23, qd + 32);
            FFMA2(a01, kp, q01, a01); FFMA2(a23, kp, q23, a23);
            PACK2(kp, kv.w); LDSV2(q01, q23, qd + 48);
            FFMA2(a01, kp, q01, a01); FFMA2(a23, kp, q23, a23);
        }
        float v0, v1, v2, v3;
        UNPACK2(v0, v1, a01); UNPACK2(v2, v3, a23);
        bool ok = (sg <= sp);
        float4 sv;
        sv.x = ok ? v0 * SCALE : -1e9f;
        sv.y = ok ? v1 * SCALE : -1e9f;
        sv.z = ok ? v2 * SCALE : -1e9f;
        sv.w = ok ? v3 * SCALE : -1e9f;
        ((float4*)ps)[64 + t] = sv;
    }
    __syncthreads();                 // bufB free; scores1 visible

    // ---- issue V1 -> bufB ----
    #pragma unroll
    for (int it = 0; it < 16; it++) {
        int row = row0 + 4 * it;
        CP_ASYNC16(bufBs + row * 528 + c4t * 16,
                   (const void*)&cvb[(s0 + 64 + row) * 32 + c4t]);
    }
    CP_COMMIT();

    // ---- softmax over this chunk (overlaps V loads): warp w = rep r ----
    {
        int w = t >> 5, l = t & 31;
        float v0 = ps[(l +  0) * 4 + w];
        float v1 = ps[(l + 32) * 4 + w];
        float v2 = ps[(l + 64) * 4 + w];
        float v3 = ps[(l + 96) * 4 + w];
        float mx = fmaxf(fmaxf(v0, v1), fmaxf(v2, v3));
        #pragma unroll
        for (int off = 16; off > 0; off >>= 1)
            mx = fmaxf(mx, __shfl_xor_sync(0xffffffffu, mx, off));
        float e0 = expf(v0 - mx), e1 = expf(v1 - mx);
        float e2 = expf(v2 - mx), e3 = expf(v3 - mx);
        float sum = e0 + e1 + e2 + e3;
        #pragma unroll
        for (int off = 16; off > 0; off >>= 1)
            sum += __shfl_xor_sync(0xffffffffu, sum, off);
        ps[(l +  0) * 4 + w] = e0;
        ps[(l + 32) * 4 + w] = e1;
        ps[(l + 64) * 4 + w] = e2;
        ps[(l + 96) * 4 + w] = e3;
        if (l == 0) { red[w] = mx; red[4 + w] = sum; }
    }

    // ================= PV tile 0 =================
    CP_WAIT(1);                      // V0 done
    __syncthreads();                 // V0 visible to all; probs visible
    if (sp >= s0 && sp < s0 + 64 && t < 32)     // patch new-token V row
        ((float4*)bufA)[(sp - s0) * 33 + t] = gv4[t];
    __syncthreads();

    unsigned long long o01 = 0ull, o23 = 0ull;
    #pragma unroll 8
    for (int s = 0; s < 64; s++) {
        float vv = bufA[s * 132 + t];
        unsigned long long vp, p01, p23;
        PACK2(vp, vv);
        LDSV2(p01, p23, psa + s * 16);
        FFMA2(o01, vp, p01, o01);
        FFMA2(o23, vp, p23, o23);
    }

    // ================= PV tile 1 =================
    CP_WAIT(0);                      // V1 done
    __syncthreads();
    if (sp >= s0 + 64 && sp < s0 + 128 && t < 32)
        ((float4*)bufB)[(sp - s0 - 64) * 33 + t] = gv4[t];
    __syncthreads();

    #pragma unroll 8
    for (int s = 0; s < 64; s++) {
        float vv = bufB[s * 132 + t];
        unsigned long long vp, p01, p23;
        PACK2(vp, vv);
        LDSV2(p01, p23, psa + (64 + s) * 16);
        FFMA2(o01, vp, p01, o01);
        FFMA2(o23, vp, p23, o23);
    }

    float o0, o1, o2, o3;
    UNPACK2(o0, o1, o01);
    UNPACK2(o2, o3, o23);
    size_t pb = ((size_t)bg * NCH + c) * REP;
    g_pacc[(pb + 0) * HD + t] = o0;
    g_pacc[(pb + 1) * HD + t] = o1;
    g_pacc[(pb + 2) * HD + t] = o2;
    g_pacc[(pb + 3) * HD + t] = o3;
    if (t < REP) { g_pm[pb + t] = red[t]; g_pl[pb + t] = red[4 + t]; }
}

// ---------------- combine split-S partials -------------------------------------
__global__ __launch_bounds__(128) void k_combine() {
    __shared__ float ms[NCH * REP], ls[NCH * REP];
    int bg = blockIdx.x, t = threadIdx.x;
    if (t < NCH * REP) {
        ms[t] = g_pm[bg * NCH * REP + t];
        ls[t] = g_pl[bg * NCH * REP + t];
    }
    __syncthreads();
    #pragma unroll
    for (int r = 0; r < REP; r++) {
        float M = -1e30f;
        #pragma unroll
        for (int cc = 0; cc < NCH; cc++) M = fmaxf(M, ms[cc * REP + r]);
        float L = 0.f, val = 0.f;
        for (int cc = 0; cc < NCH; cc++) {
            float wgt = expf(ms[cc * REP + r] - M);
            L   += ls[cc * REP + r] * wgt;
            val += g_pacc[(((size_t)bg * NCH + cc) * REP + r) * HD + t] * wgt;
        }
        g_attn[(size_t)bg * 512 + r * HD + t] = val / L;
    }
}

// ---------------- WO split-K reduce --------------------------------------------
__global__ __launch_bounds__(256) void k_wo_reduce(float* __restrict__ out) {
    int idx = blockIdx.x * 256 + threadIdx.x;            // < 32*4096
    float s = 0.f;
    #pragma unroll
    for (int p = 0; p < KSPLIT_WO; p++) s += g_wop[(size_t)p * BATCH * DIM + idx];
    out[idx] = s;
}

// ---------------- launch -------------------------------------------------------
extern "C" void kernel_launch(void* const* d_in, const int* in_sizes, int n_in,
                              void* d_out, int out_size) {
    const float* x    = (const float*)d_in[0];
    const float* wqkv = (const float*)d_in[1];
    const float* wo   = (const float*)d_in[2];
    const float* ck   = (const float*)d_in[3];
    const float* cv   = (const float*)d_in[4];
    const int*   sp   = (const int*)d_in[5];
    float*       out  = (float*)d_out;

    const int ATTN_SMEM = (512 + 512 + 16 + 2 * 8448) * 4;   // 71744 B
    static int attr_done = 0;
    if (!attr_done) {
        cudaFuncSetAttribute(k_attn3, cudaFuncAttributeMaxDynamicSharedMemorySize,
                             ATTN_SMEM);
        attr_done = 1;
    }

    k_rope_table<<<1, 64>>>(sp);
    k_gemm<QKVN, DIM / KSPLIT_QKV, false>
        <<<dim3(QKVN / 256, KSPLIT_QKV), 256>>>(x, wqkv);
    k_reduce_rope<<<(BATCH * QKVN) / 256, 256>>>();
    k_attn3<<<dim3(NCH, BATCH * NKV), 128, ATTN_SMEM>>>(ck, cv, sp);
    k_combine<<<BATCH * NKV, 128>>>();
    k_gemm<DIM, DIM / KSPLIT_WO, true>
        <<<dim3(DIM / 256, KSPLIT_WO), 256>>>(nullptr, wo);
    k_wo_reduce<<<(BATCH * DIM) / 256, 256>>>(out);
}

// round 6
// speedup vs baseline: 1.6822x; 1.1769x over previous
#include <cuda_runtime.h>
#include <cuda_bf16.h>
#include <math.h>

#define BATCH   32
#define DIM     4096
#define NKV     8
#define REP     4
#define HD      128
#define QKVN    6144      // (32 + 2*8) * 128
#define CL      2176      // cache length
#define NCH     17        // 17 * 128 = 2176
#define KSPLIT_QKV  16
#define KSPLIT_WO   32

// ---------------- f32x2 packed-math helpers -----------------------------------
#define FFMA2(d, a, b, c) \
    asm("fma.rn.f32x2 %0, %1, %2, %3;" : "=l"(d) : "l"(a), "l"(b), "l"(c))
#define PACK2(d, s) \
    asm("mov.b64 %0, {%1, %1};" : "=l"(d) : "f"(s))
#define UNPACK2(lo, hi, v) \
    asm("mov.b64 {%0, %1}, %2;" : "=f"(lo), "=f"(hi) : "l"(v))
#define LDSV2(p01, p23, addr) \
    asm("ld.shared.v2.u64 {%0, %1}, [%2];" : "=l"(p01), "=l"(p23) : "r"(addr))

// ---------------- cp.async helpers ---------------------------------------------
#define CP_ASYNC16(dst_s, src_g) \
    asm volatile("cp.async.cg.shared.global [%0], [%1], 16;" \
                 :: "r"(dst_s), "l"(src_g) : "memory")
#define CP_COMMIT() asm volatile("cp.async.commit_group;" ::: "memory")
#define CP_WAIT(n)  asm volatile("cp.async.wait_group %0;" :: "n"(n) : "memory")

// ---------------- scratch (static device globals; no allocs allowed) ----------
__device__ float g_cos[64];
__device__ float g_sin[64];
__device__ float g_qkvp[KSPLIT_QKV * BATCH * QKVN];       // 12.6 MB
__device__ float g_q[BATCH * DIM];                        // (b, g, r, d)
__device__ float g_k[BATCH * NKV * HD];
__device__ float g_v[BATCH * NKV * HD];
__device__ float g_pacc[(size_t)BATCH * NKV * NCH * REP * HD];
__device__ float g_pm[BATCH * NKV * NCH * REP];
__device__ float g_pl[BATCH * NKV * NCH * REP];
__device__ float g_attn[BATCH * DIM];
__device__ float g_wop[KSPLIT_WO * BATCH * DIM];          // 16.8 MB

// ---------------- RoPE table (double precision, tiny) -------------------------
__global__ void k_rope_table(const int* __restrict__ spp) {
    int i = threadIdx.x;
    if (i < 64) {
        int sp = *spp;
        double e    = (2.0 * (double)i) / 128.0;
        double invf = pow(10000.0, -e);
        double ang  = (double)sp * invf;
        g_cos[i] = (float)cos(ang);
        g_sin[i] = (float)sin(ang);
    }
}

// ---------------- skinny GEMM v2: 2 cols/thread, LDS.128 x-pairs ---------------
// out[32, N] partials over K-splits. grid(N/256, NSPLIT), 128 threads.
// Thread owns columns n0 = blk*256 + t and n1 = n0 + 128.
// x staged TRANSPOSED: xs_t[k][m] with row stride 36 floats (144 B, 16B-aligned)
// so 8x ld.shared.v2.u64 per k yield all 16 (m,m+1) f32x2 pairs (broadcast).
// Per k: 8 LDS.128 + 2 LDG + 2 PACK + 32 FFMA2  ->  fma-pipe bound.
template<int N, int KC, bool WO>
__global__ __launch_bounds__(128) void k_gemm2(const float* __restrict__ xsrc,
                                               const float* __restrict__ w) {
    __shared__ __align__(16) float xs_t[KC * 36];
    const int t  = threadIdx.x;
    const int k0 = blockIdx.y * KC;

    const float* xbase = WO ? (const float*)g_attn : xsrc;
    float*       obase = WO ? (float*)g_wop : (float*)g_qkvp;

    // load + transpose x chunk: [32][KC] -> xs_t[k][m]
    const float4* xg = (const float4*)xbase;
    #pragma unroll
    for (int j = t; j < 8 * KC; j += 128) {
        int m  = j / (KC / 4);
        int c4 = j % (KC / 4);
        float4 v = xg[m * (DIM / 4) + (k0 >> 2) + c4];
        xs_t[(4 * c4 + 0) * 36 + m] = v.x;
        xs_t[(4 * c4 + 1) * 36 + m] = v.y;
        xs_t[(4 * c4 + 2) * 36 + m] = v.z;
        xs_t[(4 * c4 + 3) * 36 + m] = v.w;
    }
    __syncthreads();

    const int n0 = blockIdx.x * 256 + t;
    const float* wp = w + (size_t)k0 * N + n0;
    const unsigned xa = (unsigned)__cvta_generic_to_shared(xs_t);

    unsigned long long acc0[16], acc1[16];
    #pragma unroll
    for (int mp = 0; mp < 16; mp++) { acc0[mp] = 0ull; acc1[mp] = 0ull; }

    float wb0[4], wb1[4];
    #pragma unroll
    for (int i = 0; i < 4; i++) {
        wb0[i] = wp[(size_t)i * N];
        wb1[i] = wp[(size_t)i * N + 128];
    }

    for (int kb = 0; kb < KC; kb += 4) {
        float wn0[4] = {0.f, 0.f, 0.f, 0.f};
        float wn1[4] = {0.f, 0.f, 0.f, 0.f};
        if (kb + 4 < KC) {
            #pragma unroll
            for (int i = 0; i < 4; i++) {
                wn0[i] = wp[(size_t)(kb + 4 + i) * N];
                wn1[i] = wp[(size_t)(kb + 4 + i) * N + 128];
            }
        }
        #pragma unroll
        for (int i = 0; i < 4; i++) {
            unsigned long long w0p, w1p;
            PACK2(w0p, wb0[i]);
            PACK2(w1p, wb1[i]);
            unsigned ra = xa + (kb + i) * 144;
            #pragma unroll
            for (int j = 0; j < 8; j++) {
                unsigned long long x01, x23;
                LDSV2(x01, x23, ra + j * 16);
                FFMA2(acc0[2 * j],     x01, w0p, acc0[2 * j]);
                FFMA2(acc0[2 * j + 1], x23, w0p, acc0[2 * j + 1]);
                FFMA2(acc1[2 * j],     x01, w1p, acc1[2 * j]);
                FFMA2(acc1[2 * j + 1], x23, w1p, acc1[2 * j + 1]);
            }
        }
        #pragma unroll
        for (int i = 0; i < 4; i++) { wb0[i] = wn0[i]; wb1[i] = wn1[i]; }
    }

    float* o = obase + (size_t)blockIdx.y * 32 * N + n0;
    #pragma unroll
    for (int j = 0; j < 8; j++) {
        float a, b;
        UNPACK2(a, b, acc0[2 * j]);
        o[(size_t)(4 * j) * N]     = a;
        o[(size_t)(4 * j + 1) * N] = b;
        UNPACK2(a, b, acc0[2 * j + 1]);
        o[(size_t)(4 * j + 2) * N] = a;
        o[(size_t)(4 * j + 3) * N] = b;
        UNPACK2(a, b, acc1[2 * j]);
        o[(size_t)(4 * j) * N + 128]     = a;
        o[(size_t)(4 * j + 1) * N + 128] = b;
        UNPACK2(a, b, acc1[2 * j + 1]);
        o[(size_t)(4 * j + 2) * N + 128] = a;
        o[(size_t)(4 * j + 3) * N + 128] = b;
    }
}

// ---------------- reduce QKV K-split partials + RoPE ---------------------------
__global__ __launch_bounds__(256) void k_reduce_rope() {
    int idx = blockIdx.x * 256 + threadIdx.x;            // < 32*6144
    int m = idx / QKVN;
    int n = idx % QKVN;

    float s = 0.f;
    #pragma unroll
    for (int p = 0; p < KSPLIT_QKV; p++) s += g_qkvp[((size_t)p * BATCH + m) * QKVN + n];

    if (n < 5120) {                                      // q or k: apply RoPE
        int d  = n & 127;
        int n2 = (d < 64) ? n + 64 : n - 64;
        float s2 = 0.f;
        #pragma unroll
        for (int p = 0; p < KSPLIT_QKV; p++) s2 += g_qkvp[((size_t)p * BATCH + m) * QKVN + n2];
        int i = d & 63;
        float out = (d < 64) ? s * g_cos[i] - s2 * g_sin[i]
                             : s * g_cos[i] + s2 * g_sin[i];
        if (n < 4096) g_q[m * DIM + n] = out;
        else          g_k[m * (NKV * HD) + (n - 4096)] = out;
    } else {
        g_v[m * (NKV * HD) + (n - 5120)] = s;
    }
}

// ---------------- flash-decode attention v4 ------------------------------------
// grid (NCH, 256), 128 threads. Both 64-row K tiles in flight at t=0; single
// score phase with ALL 128 threads (warps 0-1 tile A, warps 2-3 tile B).
// K/V new-token rows patched into smem. Depth-2 cp.async pipeline for V.
__global__ __launch_bounds__(128) void k_attn4(const float* __restrict__ ck,
                                               const float* __restrict__ cv,
                                               const int* __restrict__ spp) {
    extern __shared__ float sm[];
    float* qp   = sm;                 // 512 : q packed [d][4 reps]
    float* ps   = sm + 512;           // 512 : scores/probs [s][4 reps]
    float* red  = sm + 1024;          // 16  : m[0..3], l[4..7]
    float* bufA = sm + 1040;          // 8448 = 64*132
    float* bufB = sm + 1040 + 8448;   // 8448

    const int t  = threadIdx.x;
    const int c  = blockIdx.x;
    const int bg = blockIdx.y;
    const int sp = *spp;
    const float SCALE = 0.08838834764831845f;            // 1/sqrt(128)

    const float4* ckb = ((const float4*)ck) + (size_t)bg * CL * 32;
    const float4* cvb = ((const float4*)cv) + (size_t)bg * CL * 32;
    const float4* gk4 = ((const float4*)g_k) + bg * 32;
    const float4* gv4 = ((const float4*)g_v) + bg * 32;

    const unsigned qa    = (unsigned)__cvta_generic_to_shared(qp);
    const unsigned psa   = (unsigned)__cvta_generic_to_shared(ps);
    const unsigned bufAs = (unsigned)__cvta_generic_to_shared(bufA);
    const unsigned bufBs = (unsigned)__cvta_generic_to_shared(bufB);

    const int s0   = c * 128;
    const int row0 = t >> 5;          // this thread copies rows row0, row0+4, ...
    const int c4t  = t & 31;

    // ---- issue K0 -> bufA, K1 -> bufB (two groups, both in flight) ----
    #pragma unroll
    for (int it = 0; it < 16; it++) {
        int row = row0 + 4 * it;
        CP_ASYNC16(bufAs + row * 528 + c4t * 16,
                   (const void*)&ckb[(s0 + row) * 32 + c4t]);
    }
    CP_COMMIT();
    #pragma unroll
    for (int it = 0; it < 16; it++) {
        int row = row0 + 4 * it;
        CP_ASYNC16(bufBs + row * 528 + c4t * 16,
                   (const void*)&ckb[(s0 + 64 + row) * 32 + c4t]);
    }
    CP_COMMIT();

    // q packed: qp[d*4 + r]  (covered by barrier after the wait)
    #pragma unroll
    for (int it = 0; it < 4; it++) {
        int idx = t + 128 * it;
        int d = idx & 127, r = idx >> 7;
        qp[d * 4 + r] = g_q[(size_t)bg * 512 + r * 128 + d];
    }

    // ================= single score phase, all 128 threads =================
    CP_WAIT(0);
    __syncthreads();
    // patch new-token K row into smem (chunk containing sp only)
    if (sp >= s0 && sp < s0 + 128 && t < 32) {
        float* dst = (sp < s0 + 64) ? bufA + (sp - s0) * 132
                                    : bufB + (sp - s0 - 64) * 132;
        ((float4*)dst)[t] = gk4[t];
    }
    __syncthreads();
    {
        const int rloc = t & 63;
        const float4* kr = ((const float4*)((t < 64) ? bufA : bufB)) + rloc * 33;
        unsigned long long a01 = 0ull, a23 = 0ull;
        #pragma unroll 8
        for (int d4 = 0; d4 < 32; d4++) {
            float4 kv = kr[d4];
            unsigned qd = qa + d4 * 64;
            unsigned long long kp, q01, q23;
            PACK2(kp, kv.x); LDSV2(q01, q23, qd +  0);
            FFMA2(a01, kp, q01, a01); FFMA2(a23, kp, q23, a23);
            PACK2(kp, kv.y); LDSV2(q01, q23, qd + 16);
            FFMA2(a01, kp, q01, a01); FFMA2(a23, kp, q23, a23);
            PACK2(kp, kv.z); LDSV2(q01, q23, qd + 32);
            FFMA2(a01, kp, q01, a01); FFMA2(a23, kp, q23, a23);
            PACK2(kp, kv.w); LDSV2(q01, q23, qd + 48);
            FFMA2(a01, kp, q01, a01); FFMA2(a23, kp, q23, a23);
        }
        float v0, v1, v2, v3;
        UNPACK2(v0, v1, a01); UNPACK2(v2, v3, a23);
        int  sg = s0 + t;
        bool ok = (sg <= sp);
        float4 sv;
        sv.x = ok ? v0 * SCALE : -1e9f;
        sv.y = ok ? v1 * SCALE : -1e9f;
        sv.z = ok ? v2 * SCALE : -1e9f;
        sv.w = ok ? v3 * SCALE : -1e9f;
        ((float4*)ps)[t] = sv;
    }
    __syncthreads();                 // buffers free; scores visible

    // ---- issue V0 -> bufA, V1 -> bufB ----
    #pragma unroll
    for (int it = 0; it < 16; it++) {
        int row = row0 + 4 * it;
        CP_ASYNC16(bufAs + row * 528 + c4t * 16,
                   (const void*)&cvb[(s0 + row) * 32 + c4t]);
    }
    CP_COMMIT();
    #pragma unroll
    for (int it = 0; it < 16; it++) {
        int row = row0 + 4 * it;
        CP_ASYNC16(bufBs + row * 528 + c4t * 16,
                   (const void*)&cvb[(s0 + 64 + row) * 32 + c4t]);
    }
    CP_COMMIT();

    // ---- softmax over this chunk (overlaps V loads): warp w = rep r ----
    {
        int w = t >> 5, l = t & 31;
        float v0 = ps[(l +  0) * 4 + w];
        float v1 = ps[(l + 32) * 4 + w];
        float v2 = ps[(l + 64) * 4 + w];
        float v3 = ps[(l + 96) * 4 + w];
        float mx = fmaxf(fmaxf(v0, v1), fmaxf(v2, v3));
        #pragma unroll
        for (int off = 16; off > 0; off >>= 1)
            mx = fmaxf(mx, __shfl_xor_sync(0xffffffffu, mx, off));
        float e0 = expf(v0 - mx), e1 = expf(v1 - mx);
        float e2 = expf(v2 - mx), e3 = expf(v3 - mx);
        float sum = e0 + e1 + e2 + e3;
        #pragma unroll
        for (int off = 16; off > 0; off >>= 1)
            sum += __shfl_xor_sync(0xffffffffu, sum, off);
        ps[(l +  0) * 4 + w] = e0;
        ps[(l + 32) * 4 + w] = e1;
        ps[(l + 64) * 4 + w] = e2;
        ps[(l + 96) * 4 + w] = e3;
        if (l == 0) { red[w] = mx; red[4 + w] = sum; }
    }

    // ================= PV tile 0 =================
    CP_WAIT(1);                      // V0 done
    __syncthreads();                 // V0 + probs visible
    if (sp >= s0 && sp < s0 + 64 && t < 32)     // patch new-token V row
        ((float4*)bufA)[(sp - s0) * 33 + t] = gv4[t];
    __syncthreads();

    unsigned long long o01 = 0ull, o23 = 0ull;
    #pragma unroll 8
    for (int s = 0; s < 64; s++) {
        float vv = bufA[s * 132 + t];
        unsigned long long vp, p01, p23;
        PACK2(vp, vv);
        LDSV2(p01, p23, psa + s * 16);
        FFMA2(o01, vp, p01, o01);
        FFMA2(o23, vp, p23, o23);
    }

    // ================= PV tile 1 =================
    CP_WAIT(0);                      // V1 done
    __syncthreads();
    if (sp >= s0 + 64 && sp < s0 + 128 && t < 32)
        ((float4*)bufB)[(sp - s0 - 64) * 33 + t] = gv4[t];
    __syncthreads();

    #pragma unroll 8
    for (int s = 0; s < 64; s++) {
        float vv = bufB[s * 132 + t];
        unsigned long long vp, p01, p23;
        PACK2(vp, vv);
        LDSV2(p01, p23, psa + (64 + s) * 16);
        FFMA2(o01, vp, p01, o01);
        FFMA2(o23, vp, p23, o23);
    }

    float o0, o1, o2, o3;
    UNPACK2(o0, o1, o01);
    UNPACK2(o2, o3, o23);
    size_t pb = ((size_t)bg * NCH + c) * REP;
    g_pacc[(pb + 0) * HD + t] = o0;
    g_pacc[(pb + 1) * HD + t] = o1;
    g_pacc[(pb + 2) * HD + t] = o2;
    g_pacc[(pb + 3) * HD + t] = o3;
    if (t < REP) { g_pm[pb + t] = red[t]; g_pl[pb + t] = red[4 + t]; }
}

// ---------------- combine split-S partials -------------------------------------
__global__ __launch_bounds__(128) void k_combine() {
    __shared__ float ms[NCH * REP], ls[NCH * REP];
    int bg = blockIdx.x, t = threadIdx.x;
    if (t < NCH * REP) {
        ms[t] = g_pm[bg * NCH * REP + t];
        ls[t] = g_pl[bg * NCH * REP + t];
    }
    __syncthreads();
    #pragma unroll
    for (int r = 0; r < REP; r++) {
        float M = -1e30f;
        #pragma unroll
        for (int cc = 0; cc < NCH; cc++) M = fmaxf(M, ms[cc * REP + r]);
        float L = 0.f, val = 0.f;
        for (int cc = 0; cc < NCH; cc++) {
            float wgt = expf(ms[cc * REP + r] - M);
            L   += ls[cc * REP + r] * wgt;
            val += g_pacc[(((size_t)bg * NCH + cc) * REP + r) * HD + t] * wgt;
        }
        g_attn[(size_t)bg * 512 + r * HD + t] = val / L;
    }
}

// ---------------- WO split-K reduce --------------------------------------------
__global__ __launch_bounds__(256) void k_wo_reduce(float* __restrict__ out) {
    int idx = blockIdx.x * 256 + threadIdx.x;            // < 32*4096
    float s = 0.f;
    #pragma unroll
    for (int p = 0; p < KSPLIT_WO; p++) s += g_wop[(size_t)p * BATCH * DIM + idx];
    out[idx] = s;
}

// ---------------- launch -------------------------------------------------------
extern "C" void kernel_launch(void* const* d_in, const int* in_sizes, int n_in,
                              void* d_out, int out_size) {
    const float* x    = (const float*)d_in[0];
    const float* wqkv = (const float*)d_in[1];
    const float* wo   = (const float*)d_in[2];
    const float* ck   = (const float*)d_in[3];
    const float* cv   = (const float*)d_in[4];
    const int*   sp   = (const int*)d_in[5];
    float*       out  = (float*)d_out;

    const int ATTN_SMEM = (512 + 512 + 16 + 2 * 8448) * 4;   // 71744 B
    static int attr_done = 0;
    if (!attr_done) {
        cudaFuncSetAttribute(k_attn4, cudaFuncAttributeMaxDynamicSharedMemorySize,
                             ATTN_SMEM);
        attr_done = 1;
    }

    k_rope_table<<<1, 64>>>(sp);
    k_gemm2<QKVN, DIM / KSPLIT_QKV, false>
        <<<dim3(QKVN / 256, KSPLIT_QKV), 128>>>(x, wqkv);
    k_reduce_rope<<<(BATCH * QKVN) / 256, 256>>>();
    k_attn4<<<dim3(NCH, BATCH * NKV), 128, ATTN_SMEM>>>(ck, cv, sp);
    k_combine<<<BATCH * NKV, 128>>>();
    k_gemm2<DIM, DIM / KSPLIT_WO, true>
        <<<dim3(DIM / 256, KSPLIT_WO), 128>>>(nullptr, wo);
    k_wo_reduce<<<(BATCH * DIM) / 256, 256>>>(out);
}

// round 7
// speedup vs baseline: 1.7179x; 1.0212x over previous
#include <cuda_runtime.h>
#include <cuda_bf16.h>
#include <math.h>

#define BATCH   32
#define DIM     4096
#define NKV     8
#define REP     4
#define HD      128
#define QKVN    6144      // (32 + 2*8) * 128
#define CL      2176      // cache length
#define NCH     17        // 17 * 128 = 2176
#define KSPLIT_QKV  32
#define KSPLIT_WO   64

// ---------------- f32x2 packed-math helpers -----------------------------------
#define FFMA2(d, a, b, c) \
    asm("fma.rn.f32x2 %0, %1, %2, %3;" : "=l"(d) : "l"(a), "l"(b), "l"(c))
#define PACK2(d, s) \
    asm("mov.b64 %0, {%1, %1};" : "=l"(d) : "f"(s))
#define UNPACK2(lo, hi, v) \
    asm("mov.b64 {%0, %1}, %2;" : "=f"(lo), "=f"(hi) : "l"(v))
#define LDSV2(p01, p23, addr) \
    asm("ld.shared.v2.u64 {%0, %1}, [%2];" : "=l"(p01), "=l"(p23) : "r"(addr))

// ---------------- cp.async helpers ---------------------------------------------
#define CP_ASYNC16(dst_s, src_g) \
    asm volatile("cp.async.cg.shared.global [%0], [%1], 16;" \
                 :: "r"(dst_s), "l"(src_g) : "memory")
#define CP_COMMIT() asm volatile("cp.async.commit_group;" ::: "memory")
#define CP_WAIT(n)  asm volatile("cp.async.wait_group %0;" :: "n"(n) : "memory")

// ---------------- scratch (static device globals; no allocs allowed) ----------
__device__ float g_cos[64];
__device__ float g_sin[64];
__device__ float g_qkvp[KSPLIT_QKV * BATCH * QKVN];       // 25.2 MB
__device__ float g_q[BATCH * DIM];                        // (b, g, r, d)
__device__ float g_k[BATCH * NKV * HD];
__device__ float g_v[BATCH * NKV * HD];
__device__ float g_pacc[(size_t)BATCH * NKV * NCH * REP * HD];
__device__ float g_pm[BATCH * NKV * NCH * REP];
__device__ float g_pl[BATCH * NKV * NCH * REP];
__device__ float g_attn[BATCH * DIM];
__device__ float g_wop[KSPLIT_WO * BATCH * DIM];          // 33.5 MB

// ---------------- RoPE table (double precision, tiny) -------------------------
__global__ void k_rope_table(const int* __restrict__ spp) {
    int i = threadIdx.x;
    if (i < 64) {
        int sp = *spp;
        double e    = (2.0 * (double)i) / 128.0;
        double invf = pow(10000.0, -e);
        double ang  = (double)sp * invf;
        g_cos[i] = (float)cos(ang);
        g_sin[i] = (float)sin(ang);
    }
}

// ---------------- skinny GEMM v2: 2 cols/thread, LDS.128 x-pairs ---------------
// out[32, N] partials over K-splits. grid(N/256, NSPLIT), 128 threads.
// Thread owns columns n0 = blk*256 + t and n1 = n0 + 128.
// x staged TRANSPOSED: xs_t[k][m] with row stride 36 floats (144 B, 16B-aligned)
// so 8x ld.shared.v2.u64 per k yield all 16 (m,m+1) f32x2 pairs (broadcast).
// Per k: 8 LDS.128 + 2 LDG + 2 PACK + 32 FFMA2  ->  fma-pipe bound.
template<int N, int KC, bool WO>
__global__ __launch_bounds__(128) void k_gemm2(const float* __restrict__ xsrc,
                                               const float* __restrict__ w) {
    __shared__ __align__(16) float xs_t[KC * 36];
    const int t  = threadIdx.x;
    const int k0 = blockIdx.y * KC;

    const float* xbase = WO ? (const float*)g_attn : xsrc;
    float*       obase = WO ? (float*)g_wop : (float*)g_qkvp;

    // load + transpose x chunk: [32][KC] -> xs_t[k][m]
    const float4* xg = (const float4*)xbase;
    #pragma unroll
    for (int j = t; j < 8 * KC; j += 128) {
        int m  = j / (KC / 4);
        int c4 = j % (KC / 4);
        float4 v = xg[m * (DIM / 4) + (k0 >> 2) + c4];
        xs_t[(4 * c4 + 0) * 36 + m] = v.x;
        xs_t[(4 * c4 + 1) * 36 + m] = v.y;
        xs_t[(4 * c4 + 2) * 36 + m] = v.z;
        xs_t[(4 * c4 + 3) * 36 + m] = v.w;
    }
    __syncthreads();

    const int n0 = blockIdx.x * 256 + t;
    const float* wp = w + (size_t)k0 * N + n0;
    const unsigned xa = (unsigned)__cvta_generic_to_shared(xs_t);

    unsigned long long acc0[16], acc1[16];
    #pragma unroll
    for (int mp = 0; mp < 16; mp++) { acc0[mp] = 0ull; acc1[mp] = 0ull; }

    float wb0[4], wb1[4];
    #pragma unroll
    for (int i = 0; i < 4; i++) {
        wb0[i] = wp[(size_t)i * N];
        wb1[i] = wp[(size_t)i * N + 128];
    }

    for (int kb = 0; kb < KC; kb += 4) {
        float wn0[4] = {0.f, 0.f, 0.f, 0.f};
        float wn1[4] = {0.f, 0.f, 0.f, 0.f};
        if (kb + 4 < KC) {
            #pragma unroll
            for (int i = 0; i < 4; i++) {
                wn0[i] = wp[(size_t)(kb + 4 + i) * N];
                wn1[i] = wp[(size_t)(kb + 4 + i) * N + 128];
            }
        }
        #pragma unroll
        for (int i = 0; i < 4; i++) {
            unsigned long long w0p, w1p;
            PACK2(w0p, wb0[i]);
            PACK2(w1p, wb1[i]);
            unsigned ra = xa + (kb + i) * 144;
            #pragma unroll
            for (int j = 0; j < 8; j++) {
                unsigned long long x01, x23;
                LDSV2(x01, x23, ra + j * 16);
                FFMA2(acc0[2 * j],     x01, w0p, acc0[2 * j]);
                FFMA2(acc0[2 * j + 1], x23, w0p, acc0[2 * j + 1]);
                FFMA2(acc1[2 * j],     x01, w1p, acc1[2 * j]);
                FFMA2(acc1[2 * j + 1], x23, w1p, acc1[2 * j + 1]);
            }
        }
        #pragma unroll
        for (int i = 0; i < 4; i++) { wb0[i] = wn0[i]; wb1[i] = wn1[i]; }
    }

    float* o = obase + (size_t)blockIdx.y * 32 * N + n0;
    #pragma unroll
    for (int j = 0; j < 8; j++) {
        float a, b;
        UNPACK2(a, b, acc0[2 * j]);
        o[(size_t)(4 * j) * N]     = a;
        o[(size_t)(4 * j + 1) * N] = b;
        UNPACK2(a, b, acc0[2 * j + 1]);
        o[(size_t)(4 * j + 2) * N] = a;
        o[(size_t)(4 * j + 3) * N] = b;
        UNPACK2(a, b, acc1[2 * j]);
        o[(size_t)(4 * j) * N + 128]     = a;
        UNPACK2(a, b, acc1[2 * j]);
        o[(size_t)(4 * j + 1) * N + 128] = b;
        UNPACK2(a, b, acc1[2 * j + 1]);
        o[(size_t)(4 * j + 2) * N + 128] = a;
        o[(size_t)(4 * j + 3) * N + 128] = b;
    }
}

// ---------------- reduce QKV K-split partials + RoPE (pairwise) ----------------
// q/k: one thread handles the (d, d+64) rotation pair -> each partial read once.
// idx < 32*2560 : q/k pairs (40 heads x 64 low dims). Else: v passthrough.
__global__ __launch_bounds__(256) void k_reduce_rope() {
    int idx = blockIdx.x * 256 + threadIdx.x;

    if (idx < BATCH * 2560) {
        int m = idx / 2560;
        int p = idx % 2560;
        int h = p >> 6;                                  // head 0..39 (q then k)
        int i = p & 63;                                  // low dim
        int n  = h * 128 + i;
        int n2 = n + 64;

        float s = 0.f, s2 = 0.f;
        #pragma unroll
        for (int sp = 0; sp < KSPLIT_QKV; sp++) {
            const float* base = g_qkvp + ((size_t)sp * BATCH + m) * QKVN;
            s  += base[n];
            s2 += base[n2];
        }
        float co = g_cos[i], si = g_sin[i];
        float out1 = s * co - s2 * si;
        float out2 = s2 * co + s * si;
        if (n < 4096) {
            g_q[m * DIM + n]  = out1;
            g_q[m * DIM + n2] = out2;
        } else {
            g_k[m * (NKV * HD) + (n - 4096)]  = out1;
            g_k[m * (NKV * HD) + (n2 - 4096)] = out2;
        }
    } else if (idx < BATCH * 2560 + BATCH * 1024) {
        int j = idx - BATCH * 2560;
        int m = j >> 10;
        int n = 5120 + (j & 1023);
        float s = 0.f;
        #pragma unroll
        for (int sp = 0; sp < KSPLIT_QKV; sp++)
            s += g_qkvp[((size_t)sp * BATCH + m) * QKVN + n];
        g_v[m * (NKV * HD) + (n - 5120)] = s;
    }
}

// ---------------- flash-decode attention v5: per-warp decoupled pipeline -------
// grid (NCH, 256), 128 threads. Warp w owns rows [32w, 32w+32) of the chunk:
// issues its own cp.async group for K, waits ONLY its group, scores its rows,
// then immediately issues its V rows. Block barriers only where softmax truly
// needs all scores. Memory stays busy while other warps compute.
__global__ __launch_bounds__(128) void k_attn5(const float* __restrict__ ck,
                                               const float* __restrict__ cv,
                                               const int* __restrict__ spp) {
    extern __shared__ float sm[];
    float* qp  = sm;                  // 512 : q packed [d][4 reps]
    float* ps  = sm + 512;            // 512 : scores/probs [s][4 reps]
    float* red = sm + 1024;           // 16  : m[0..3], l[4..7]
    float* kvs = sm + 1040;           // 16896 = 128*132 (K tile, then V tile)

    const int t  = threadIdx.x;
    const int w  = t >> 5;
    const int l  = t & 31;
    const int c  = blockIdx.x;
    const int bg = blockIdx.y;
    const int sp = *spp;
    const float SCALE = 0.08838834764831845f;            // 1/sqrt(128)

    const float4* ckb = ((const float4*)ck) + (size_t)bg * CL * 32;
    const float4* cvb = ((const float4*)cv) + (size_t)bg * CL * 32;
    const float4* gk4 = ((const float4*)g_k) + bg * 32;
    const float4* gv4 = ((const float4*)g_v) + bg * 32;

    const unsigned qa   = (unsigned)__cvta_generic_to_shared(qp);
    const unsigned psa  = (unsigned)__cvta_generic_to_shared(ps);
    const unsigned kvsa = (unsigned)__cvta_generic_to_shared(kvs);

    const int s0  = c * 128;
    const int rw0 = w * 32;           // this warp's first row

    // ---- warp w issues K for its 32 rows (one commit group per thread) ----
    #pragma unroll
    for (int it = 0; it < 32; it++) {
        int j   = l + 32 * it;        // 0..1023
        int row = rw0 + (j >> 5);
        int c4  = j & 31;
        CP_ASYNC16(kvsa + row * 528 + c4 * 16,
                   (const void*)&ckb[(s0 + row) * 32 + c4]);
    }
    CP_COMMIT();

    // q packed: qp[d*4 + r] (all threads)
    #pragma unroll
    for (int it = 0; it < 4; it++) {
        int idx = t + 128 * it;
        int d = idx & 127, r = idx >> 7;
        qp[d * 4 + r] = g_q[(size_t)bg * 512 + r * 128 + d];
    }
    __syncthreads();                  // qp visible (K loads still in flight)

    // ---- per-warp: wait own K, patch new-token row, score own rows ----
    CP_WAIT(0);
    __syncwarp();
    if (sp >= s0 + rw0 && sp < s0 + rw0 + 32)
        ((float4*)(kvs + (sp - s0) * 132))[l] = gk4[l];
    __syncwarp();
    {
        const int rloc = rw0 + l;
        const float4* kr = ((const float4*)kvs) + rloc * 33;
        unsigned long long a01 = 0ull, a23 = 0ull;
        #pragma unroll 8
        for (int d4 = 0; d4 < 32; d4++) {
            float4 kv = kr[d4];
            unsigned qd = qa + d4 * 64;
            unsigned long long kp, q01, q23;
            PACK2(kp, kv.x); LDSV2(q01, q23, qd +  0);
            FFMA2(a01, kp, q01, a01); FFMA2(a23, kp, q23, a23);
            PACK2(kp, kv.y); LDSV2(q01, q23, qd + 16);
            FFMA2(a01, kp, q01, a01); FFMA2(a23, kp, q23, a23);
            PACK2(kp, kv.z); LDSV2(q01, q23, qd + 32);
            FFMA2(a01, kp, q01, a01); FFMA2(a23, kp, q23, a23);
            PACK2(kp, kv.w); LDSV2(q01, q23, qd + 48);
            FFMA2(a01, kp, q01, a01); FFMA2(a23, kp, q23, a23);
        }
        float v0, v1, v2, v3;
        UNPACK2(v0, v1, a01); UNPACK2(v2, v3, a23);
        int  sg = s0 + rloc;
        bool ok = (sg <= sp);
        float4 sv;
        sv.x = ok ? v0 * SCALE : -1e9f;
        sv.y = ok ? v1 * SCALE : -1e9f;
        sv.z = ok ? v2 * SCALE : -1e9f;
        sv.w = ok ? v3 * SCALE : -1e9f;
        ((float4*)ps)[rloc] = sv;
    }

    // ---- immediately issue V for own rows (overwrites own K region) ----
    #pragma unroll
    for (int it = 0; it < 32; it++) {
        int j   = l + 32 * it;
        int row = rw0 + (j >> 5);
        int c4  = j & 31;
        CP_ASYNC16(kvsa + row * 528 + c4 * 16,
                   (const void*)&cvb[(s0 + row) * 32 + c4]);
    }
    CP_COMMIT();

    __syncthreads();                  // all scores in ps

    // ---- softmax over this chunk: warp w handles rep r = w ----
    {
        float v0 = ps[(l +  0) * 4 + w];
        float v1 = ps[(l + 32) * 4 + w];
        float v2 = ps[(l + 64) * 4 + w];
        float v3 = ps[(l + 96) * 4 + w];
        float mx = fmaxf(fmaxf(v0, v1), fmaxf(v2, v3));
        #pragma unroll
        for (int off = 16; off > 0; off >>= 1)
            mx = fmaxf(mx, __shfl_xor_sync(0xffffffffu, mx, off));
        float e0 = expf(v0 - mx), e1 = expf(v1 - mx);
        float e2 = expf(v2 - mx), e3 = expf(v3 - mx);
        float sum = e0 + e1 + e2 + e3;
        #pragma unroll
        for (int off = 16; off > 0; off >>= 1)
            sum += __shfl_xor_sync(0xffffffffu, sum, off);
        ps[(l +  0) * 4 + w] = e0;
        ps[(l + 32) * 4 + w] = e1;
        ps[(l + 64) * 4 + w] = e2;
        ps[(l + 96) * 4 + w] = e3;
        if (l == 0) { red[w] = mx; red[4 + w] = sum; }
    }

    // ---- wait own V, patch own-range new-token V row ----
    CP_WAIT(0);
    __syncwarp();
    if (sp >= s0 + rw0 && sp < s0 + rw0 + 32)
        ((float4*)(kvs + (sp - s0) * 132))[l] = gv4[l];
    __syncthreads();                  // all V rows + all probs visible

    // ---- PV: thread t owns head dim d = t, full 128 rows ----
    unsigned long long o01 = 0ull, o23 = 0ull;
    #pragma unroll 8
    for (int s = 0; s < 128; s++) {
        float vv = kvs[s * 132 + t];
        unsigned long long vp, p01, p23;
        PACK2(vp, vv);
        LDSV2(p01, p23, psa + s * 16);
        FFMA2(o01, vp, p01, o01);
        FFMA2(o23, vp, p23, o23);
    }

    float o0, o1, o2, o3;
    UNPACK2(o0, o1, o01);
    UNPACK2(o2, o3, o23);
    size_t pb = ((size_t)bg * NCH + c) * REP;
    g_pacc[(pb + 0) * HD + t] = o0;
    g_pacc[(pb + 1) * HD + t] = o1;
    g_pacc[(pb + 2) * HD + t] = o2;
    g_pacc[(pb + 3) * HD + t] = o3;
    if (t < REP) { g_pm[pb + t] = red[t]; g_pl[pb + t] = red[4 + t]; }
}

// ---------------- combine split-S partials -------------------------------------
__global__ __launch_bounds__(128) void k_combine() {
    __shared__ float ms[NCH * REP], ls[NCH * REP];
    int bg = blockIdx.x, t = threadIdx.x;
    if (t < NCH * REP) {
        ms[t] = g_pm[bg * NCH * REP + t];
        ls[t] = g_pl[bg * NCH * REP + t];
    }
    __syncthreads();
    #pragma unroll
    for (int r = 0; r < REP; r++) {
        float M = -1e30f;
        #pragma unroll
        for (int cc = 0; cc < NCH; cc++) M = fmaxf(M, ms[cc * REP + r]);
        float L = 0.f, val = 0.f;
        for (int cc = 0; cc < NCH; cc++) {
            float wgt = expf(ms[cc * REP + r] - M);
            L   += ls[cc * REP + r] * wgt;
            val += g_pacc[(((size_t)bg * NCH + cc) * REP + r) * HD + t] * wgt;
        }
        g_attn[(size_t)bg * 512 + r * HD + t] = val / L;
    }
}

// ---------------- WO split-K reduce --------------------------------------------
__global__ __launch_bounds__(256) void k_wo_reduce(float* __restrict__ out) {
    int idx = blockIdx.x * 256 + threadIdx.x;            // < 32*4096
    float s = 0.f;
    #pragma unroll
    for (int p = 0; p < KSPLIT_WO; p++) s += g_wop[(size_t)p * BATCH * DIM + idx];
    out[idx] = s;
}

// ---------------- launch -------------------------------------------------------
extern "C" void kernel_launch(void* const* d_in, const int* in_sizes, int n_in,
                              void* d_out, int out_size) {
    const float* x    = (const float*)d_in[0];
    const float* wqkv = (const float*)d_in[1];
    const float* wo   = (const float*)d_in[2];
    const float* ck   = (const float*)d_in[3];
    const float* cv   = (const float*)d_in[4];
    const int*   sp   = (const int*)d_in[5];
    float*       out  = (float*)d_out;

    const int ATTN_SMEM = (512 + 512 + 16 + 16896) * 4;   // 71744 B
    static int attr_done = 0;
    if (!attr_done) {
        cudaFuncSetAttribute(k_attn5, cudaFuncAttributeMaxDynamicSharedMemorySize,
                             ATTN_SMEM);
        attr_done = 1;
    }

    k_rope_table<<<1, 64>>>(sp);
    k_gemm2<QKVN, DIM / KSPLIT_QKV, false>
        <<<dim3(QKVN / 256, KSPLIT_QKV), 128>>>(x, wqkv);
    k_reduce_rope<<<(BATCH * 2560 + BATCH * 1024 + 255) / 256, 256>>>();
    k_attn5<<<dim3(NCH, BATCH * NKV), 128, ATTN_SMEM>>>(ck, cv, sp);
    k_combine<<<BATCH * NKV, 128>>>();
    k_gemm2<DIM, DIM / KSPLIT_WO, true>
        <<<dim3(DIM / 256, KSPLIT_WO), 128>>>(nullptr, wo);
    k_wo_reduce<<<(BATCH * DIM) / 256, 256>>>(out);
}

// round 8
// speedup vs baseline: 1.8231x; 1.0613x over previous
#include <cuda_runtime.h>
#include <cuda_bf16.h>
#include <math.h>

#define BATCH   32
#define DIM     4096
#define NKV     8
#define REP     4
#define HD      128
#define QKVN    6144      // (32 + 2*8) * 128
#define CL      2176      // cache length
#define NCH     17        // 17 * 128 = 2176
#define KSPLIT_QKV  16
#define KSPLIT_WO   32

// ---------------- f32x2 packed-math helpers -----------------------------------
#define FFMA2(d, a, b, c) \
    asm("fma.rn.f32x2 %0, %1, %2, %3;" : "=l"(d) : "l"(a), "l"(b), "l"(c))
#define PACK2(d, s) \
    asm("mov.b64 %0, {%1, %1};" : "=l"(d) : "f"(s))
#define UNPACK2(lo, hi, v) \
    asm("mov.b64 {%0, %1}, %2;" : "=f"(lo), "=f"(hi) : "l"(v))
#define LDSV2(p01, p23, addr) \
    asm("ld.shared.v2.u64 {%0, %1}, [%2];" : "=l"(p01), "=l"(p23) : "r"(addr))

// ---------------- cp.async helpers ---------------------------------------------
#define CP_ASYNC16(dst_s, src_g) \
    asm volatile("cp.async.cg.shared.global [%0], [%1], 16;" \
                 :: "r"(dst_s), "l"(src_g) : "memory")
#define CP_COMMIT() asm volatile("cp.async.commit_group;" ::: "memory")
#define CP_WAIT(n)  asm volatile("cp.async.wait_group %0;" :: "n"(n) : "memory")

// ---------------- scratch (static device globals; no allocs allowed) ----------
__device__ float g_qkvp[KSPLIT_QKV * BATCH * QKVN];       // 12.6 MB
__device__ float g_q[BATCH * DIM];                        // (b, g, r, d)
__device__ float g_k[BATCH * NKV * HD];
__device__ float g_v[BATCH * NKV * HD];
__device__ float g_pacc[(size_t)BATCH * NKV * NCH * REP * HD];
__device__ float g_pm[BATCH * NKV * NCH * REP];
__device__ float g_pl[BATCH * NKV * NCH * REP];
__device__ float g_attn[BATCH * DIM];
__device__ float g_wop[KSPLIT_WO * BATCH * DIM];          // 16.8 MB

// ---------------- skinny GEMM v3: cp.async weight staging ----------------------
// out[32, N] partials over K-splits. grid(N/256, NSPLIT), 128 threads.
// Thread owns ADJACENT columns n0 = blk*256 + 2t, n1 = n0 + 1.
// x transposed in smem: xs_t[k][m], stride 36 floats (16B-aligned rows).
// Weights stream via cp.async in 16-row x 256-col chunks, double-buffered:
// DRAM latency fully decoupled from the FFMA2 stream.
template<int N, int KC, bool WO>
__global__ __launch_bounds__(128) void k_gemm3(const float* __restrict__ xsrc,
                                               const float* __restrict__ w) {
    extern __shared__ float smg[];
    float* xs_t = smg;                 // KC * 36 floats
    float* wt   = smg + KC * 36;       // 2 * 16 * 256 floats

    const int t    = threadIdx.x;
    const int k0   = blockIdx.y * KC;
    const int nblk = blockIdx.x * 256;
    constexpr int NCHW = KC / 16;      // weight chunks

    const float* xbase = WO ? (const float*)g_attn : xsrc;
    float*       obase = WO ? (float*)g_wop : (float*)g_qkvp;

    const unsigned wts = (unsigned)__cvta_generic_to_shared(wt);

    // issue weight chunk cb (16 rows x 256 cols = 16 KB) into buffer cb&1
    auto issue = [&](int cb) {
        const float* src = w + (size_t)(k0 + cb * 16) * N + nblk;
        unsigned dst = wts + (cb & 1) * 16384;
        #pragma unroll
        for (int it = 0; it < 8; it++) {
            int idx = t + 128 * it;            // 0..1023
            int row = idx >> 6;                // 64 x 16B per row
            int c16 = idx & 63;
            CP_ASYNC16(dst + (row * 256 + c16 * 4) * 4,
                       (const void*)(src + (size_t)row * N + c16 * 4));
        }
        CP_COMMIT();
    };
    issue(0);
    issue(1);

    // load + transpose x chunk: [32][KC] -> xs_t[k][m]
    const float4* xg = (const float4*)xbase;
    #pragma unroll
    for (int j = t; j < 8 * KC; j += 128) {
        int m  = j / (KC / 4);
        int c4 = j % (KC / 4);
        float4 v = xg[m * (DIM / 4) + (k0 >> 2) + c4];
        xs_t[(4 * c4 + 0) * 36 + m] = v.x;
        xs_t[(4 * c4 + 1) * 36 + m] = v.y;
        xs_t[(4 * c4 + 2) * 36 + m] = v.z;
        xs_t[(4 * c4 + 3) * 36 + m] = v.w;
    }

    const unsigned xa = (unsigned)__cvta_generic_to_shared(xs_t);

    unsigned long long acc0[16], acc1[16];
    #pragma unroll
    for (int mp = 0; mp < 16; mp++) { acc0[mp] = 0ull; acc1[mp] = 0ull; }

    for (int cb = 0; cb < NCHW; cb++) {
        CP_WAIT(1);
        __syncthreads();               // chunk cb present (+ xs_t on cb==0)
        const float* wchunk = wt + (cb & 1) * 4096;
        #pragma unroll
        for (int kk = 0; kk < 16; kk++) {
            float2 wv = *(const float2*)&wchunk[kk * 256 + 2 * t];
            unsigned long long w0p, w1p;
            PACK2(w0p, wv.x);
            PACK2(w1p, wv.y);
            unsigned ra = xa + (cb * 16 + kk) * 144;
            #pragma unroll
            for (int j = 0; j < 8; j++) {
                unsigned long long x01, x23;
                LDSV2(x01, x23, ra + j * 16);
                FFMA2(acc0[2 * j],     x01, w0p, acc0[2 * j]);
                FFMA2(acc0[2 * j + 1], x23, w0p, acc0[2 * j + 1]);
                FFMA2(acc1[2 * j],     x01, w1p, acc1[2 * j]);
                FFMA2(acc1[2 * j + 1], x23, w1p, acc1[2 * j + 1]);
            }
        }
        __syncthreads();               // all reads of buffer cb&1 done
        if (cb + 2 < NCHW) issue(cb + 2);
    }

    // epilogue: row m gets columns (2t, 2t+1) -> one float2 store per row
    float* o = obase + (size_t)blockIdx.y * 32 * N + nblk + 2 * t;
    #pragma unroll
    for (int mp = 0; mp < 16; mp++) {
        float a0, b0, a1, b1;
        UNPACK2(a0, b0, acc0[mp]);
        UNPACK2(a1, b1, acc1[mp]);
        float2 lo = make_float2(a0, a1);
        float2 hi = make_float2(b0, b1);
        *(float2*)&o[(size_t)(2 * mp) * N]     = lo;
        *(float2*)&o[(size_t)(2 * mp + 1) * N] = hi;
    }
}

// ---------------- reduce QKV K-split partials + RoPE (pairwise, fused table) ---
// q/k: one thread handles the (d, d+64) rotation pair -> each partial read once.
// RoPE cos/sin computed per-block in smem (double precision, 64 values).
__global__ __launch_bounds__(256) void k_reduce_rope(const int* __restrict__ spp) {
    __shared__ float cs[64], sn[64];
    int tt = threadIdx.x;
    if (tt < 64) {
        int sp = *spp;
        double e    = (2.0 * (double)tt) / 128.0;
        double invf = pow(10000.0, -e);
        double ang  = (double)sp * invf;
        cs[tt] = (float)cos(ang);
        sn[tt] = (float)sin(ang);
    }
    __syncthreads();

    int idx = blockIdx.x * 256 + tt;

    if (idx < BATCH * 2560) {
        int m = idx / 2560;
        int p = idx % 2560;
        int h = p >> 6;                                  // head 0..39 (q then k)
        int i = p & 63;                                  // low dim
        int n  = h * 128 + i;
        int n2 = n + 64;

        float s = 0.f, s2 = 0.f;
        #pragma unroll
        for (int sp = 0; sp < KSPLIT_QKV; sp++) {
            const float* base = g_qkvp + ((size_t)sp * BATCH + m) * QKVN;
            s  += base[n];
            s2 += base[n2];
        }
        float co = cs[i], si = sn[i];
        float out1 = s * co - s2 * si;
        float out2 = s2 * co + s * si;
        if (n < 4096) {
            g_q[m * DIM + n]  = out1;
            g_q[m * DIM + n2] = out2;
        } else {
            g_k[m * (NKV * HD) + (n - 4096)]  = out1;
            g_k[m * (NKV * HD) + (n2 - 4096)] = out2;
        }
    } else if (idx < BATCH * 2560 + BATCH * 1024) {
        int j = idx - BATCH * 2560;
        int m = j >> 10;
        int n = 5120 + (j & 1023);
        float s = 0.f;
        #pragma unroll
        for (int sp = 0; sp < KSPLIT_QKV; sp++)
            s += g_qkvp[((size_t)sp * BATCH + m) * QKVN + n];
        g_v[m * (NKV * HD) + (n - 5120)] = s;
    }
}

// ---------------- flash-decode attention v5: per-warp decoupled pipeline -------
__global__ __launch_bounds__(128) void k_attn5(const float* __restrict__ ck,
                                               const float* __restrict__ cv,
                                               const int* __restrict__ spp) {
    extern __shared__ float sm[];
    float* qp  = sm;                  // 512 : q packed [d][4 reps]
    float* ps  = sm + 512;            // 512 : scores/probs [s][4 reps]
    float* red = sm + 1024;           // 16  : m[0..3], l[4..7]
    float* kvs = sm + 1040;           // 16896 = 128*132 (K tile, then V tile)

    const int t  = threadIdx.x;
    const int w  = t >> 5;
    const int l  = t & 31;
    const int c  = blockIdx.x;
    const int bg = blockIdx.y;
    const int sp = *spp;
    const float SCALE = 0.08838834764831845f;            // 1/sqrt(128)

    const float4* ckb = ((const float4*)ck) + (size_t)bg * CL * 32;
    const float4* cvb = ((const float4*)cv) + (size_t)bg * CL * 32;
    const float4* gk4 = ((const float4*)g_k) + bg * 32;
    const float4* gv4 = ((const float4*)g_v) + bg * 32;

    const unsigned qa   = (unsigned)__cvta_generic_to_shared(qp);
    const unsigned psa  = (unsigned)__cvta_generic_to_shared(ps);
    const unsigned kvsa = (unsigned)__cvta_generic_to_shared(kvs);

    const int s0  = c * 128;
    const int rw0 = w * 32;           // this warp's first row

    // ---- warp w issues K for its 32 rows ----
    #pragma unroll
    for (int it = 0; it < 32; it++) {
        int j   = l + 32 * it;
        int row = rw0 + (j >> 5);
        int c4  = j & 31;
        CP_ASYNC16(kvsa + row * 528 + c4 * 16,
                   (const void*)&ckb[(s0 + row) * 32 + c4]);
    }
    CP_COMMIT();

    // q packed: qp[d*4 + r] (all threads)
    #pragma unroll
    for (int it = 0; it < 4; it++) {
        int idx = t + 128 * it;
        int d = idx & 127, r = idx >> 7;
        qp[d * 4 + r] = g_q[(size_t)bg * 512 + r * 128 + d];
    }
    __syncthreads();                  // qp visible (K loads still in flight)

    // ---- per-warp: wait own K, patch new-token row, score own rows ----
    CP_WAIT(0);
    __syncwarp();
    if (sp >= s0 + rw0 && sp < s0 + rw0 + 32)
        ((float4*)(kvs + (sp - s0) * 132))[l] = gk4[l];
    __syncwarp();
    {
        const int rloc = rw0 + l;
        const float4* kr = ((const float4*)kvs) + rloc * 33;
        unsigned long long a01 = 0ull, a23 = 0ull;
        #pragma unroll 8
        for (int d4 = 0; d4 < 32; d4++) {
            float4 kv = kr[d4];
            unsigned qd = qa + d4 * 64;
            unsigned long long kp, q01, q23;
            PACK2(kp, kv.x); LDSV2(q01, q23, qd +  0);
            FFMA2(a01, kp, q01, a01); FFMA2(a23, kp, q23, a23);
            PACK2(kp, kv.y); LDSV2(q01, q23, qd + 16);
            FFMA2(a01, kp, q01, a01); FFMA2(a23, kp, q23, a23);
            PACK2(kp, kv.z); LDSV2(q01, q23, qd + 32);
            FFMA2(a01, kp, q01, a01); FFMA2(a23, kp, q23, a23);
            PACK2(kp, kv.w); LDSV2(q01, q23, qd + 48);
            FFMA2(a01, kp, q01, a01); FFMA2(a23, kp, q23, a23);
        }
        float v0, v1, v2, v3;
        UNPACK2(v0, v1, a01); UNPACK2(v2, v3, a23);
        int  sg = s0 + rloc;
        bool ok = (sg <= sp);
        float4 sv;
        sv.x = ok ? v0 * SCALE : -1e9f;
        sv.y = ok ? v1 * SCALE : -1e9f;
        sv.z = ok ? v2 * SCALE : -1e9f;
        sv.w = ok ? v3 * SCALE : -1e9f;
        ((float4*)ps)[rloc] = sv;
    }

    // ---- immediately issue V for own rows (overwrites own K region) ----
    #pragma unroll
    for (int it = 0; it < 32; it++) {
        int j   = l + 32 * it;
        int row = rw0 + (j >> 5);
        int c4  = j & 31;
        CP_ASYNC16(kvsa + row * 528 + c4 * 16,
                   (const void*)&cvb[(s0 + row) * 32 + c4]);
    }
    CP_COMMIT();

    __syncthreads();                  // all scores in ps

    // ---- softmax over this chunk: warp w handles rep r = w ----
    {
        float v0 = ps[(l +  0) * 4 + w];
        float v1 = ps[(l + 32) * 4 + w];
        float v2 = ps[(l + 64) * 4 + w];
        float v3 = ps[(l + 96) * 4 + w];
        float mx = fmaxf(fmaxf(v0, v1), fmaxf(v2, v3));
        #pragma unroll
        for (int off = 16; off > 0; off >>= 1)
            mx = fmaxf(mx, __shfl_xor_sync(0xffffffffu, mx, off));
        float e0 = expf(v0 - mx), e1 = expf(v1 - mx);
        float e2 = expf(v2 - mx), e3 = expf(v3 - mx);
        float sum = e0 + e1 + e2 + e3;
        #pragma unroll
        for (int off = 16; off > 0; off >>= 1)
            sum += __shfl_xor_sync(0xffffffffu, sum, off);
        ps[(l +  0) * 4 + w] = e0;
        ps[(l + 32) * 4 + w] = e1;
        ps[(l + 64) * 4 + w] = e2;
        ps[(l + 96) * 4 + w] = e3;
        if (l == 0) { red[w] = mx; red[4 + w] = sum; }
    }

    // ---- wait own V, patch own-range new-token V row ----
    CP_WAIT(0);
    __syncwarp();
    if (sp >= s0 + rw0 && sp < s0 + rw0 + 32)
        ((float4*)(kvs + (sp - s0) * 132))[l] = gv4[l];
    __syncthreads();                  // all V rows + all probs visible

    // ---- PV: thread t owns head dim d = t, full 128 rows ----
    unsigned long long o01 = 0ull, o23 = 0ull;
    #pragma unroll 8
    for (int s = 0; s < 128; s++) {
        float vv = kvs[s * 132 + t];
        unsigned long long vp, p01, p23;
        PACK2(vp, vv);
        LDSV2(p01, p23, psa + s * 16);
        FFMA2(o01, vp, p01, o01);
        FFMA2(o23, vp, p23, o23);
    }

    float o0, o1, o2, o3;
    UNPACK2(o0, o1, o01);
    UNPACK2(o2, o3, o23);
    size_t pb = ((size_t)bg * NCH + c) * REP;
    g_pacc[(pb + 0) * HD + t] = o0;
    g_pacc[(pb + 1) * HD + t] = o1;
    g_pacc[(pb + 2) * HD + t] = o2;
    g_pacc[(pb + 3) * HD + t] = o3;
    if (t < REP) { g_pm[pb + t] = red[t]; g_pl[pb + t] = red[4 + t]; }
}

// ---------------- combine split-S partials -------------------------------------
__global__ __launch_bounds__(128) void k_combine() {
    __shared__ float ms[NCH * REP], ls[NCH * REP];
    int bg = blockIdx.x, t = threadIdx.x;
    if (t < NCH * REP) {
        ms[t] = g_pm[bg * NCH * REP + t];
        ls[t] = g_pl[bg * NCH * REP + t];
    }
    __syncthreads();
    #pragma unroll
    for (int r = 0; r < REP; r++) {
        float M = -1e30f;
        #pragma unroll
        for (int cc = 0; cc < NCH; cc++) M = fmaxf(M, ms[cc * REP + r]);
        float L = 0.f, val = 0.f;
        for (int cc = 0; cc < NCH; cc++) {
            float wgt = expf(ms[cc * REP + r] - M);
            L   += ls[cc * REP + r] * wgt;
            val += g_pacc[(((size_t)bg * NCH + cc) * REP + r) * HD + t] * wgt;
        }
        g_attn[(size_t)bg * 512 + r * HD + t] = val / L;
    }
}

// ---------------- WO split-K reduce --------------------------------------------
__global__ __launch_bounds__(256) void k_wo_reduce(float* __restrict__ out) {
    int idx = blockIdx.x * 256 + threadIdx.x;            // < 32*4096
    float s = 0.f;
    #pragma unroll
    for (int p = 0; p < KSPLIT_WO; p++) s += g_wop[(size_t)p * BATCH * DIM + idx];
    out[idx] = s;
}

// ---------------- launch -------------------------------------------------------
extern "C" void kernel_launch(void* const* d_in, const int* in_sizes, int n_in,
                              void* d_out, int out_size) {
    const float* x    = (const float*)d_in[0];
    const float* wqkv = (const float*)d_in[1];
    const float* wo   = (const float*)d_in[2];
    const float* ck   = (const float*)d_in[3];
    const float* cv   = (const float*)d_in[4];
    const int*   sp   = (const int*)d_in[5];
    float*       out  = (float*)d_out;

    const int ATTN_SMEM = (512 + 512 + 16 + 16896) * 4;            // 71744 B
    const int QKV_SMEM  = ((DIM / KSPLIT_QKV) * 36 + 8192) * 4;    // 69632 B
    const int WO_SMEM   = ((DIM / KSPLIT_WO) * 36 + 8192) * 4;     // 51200 B
    static int attr_done = 0;
    if (!attr_done) {
        cudaFuncSetAttribute(k_attn5, cudaFuncAttributeMaxDynamicSharedMemorySize,
                             ATTN_SMEM);
        cudaFuncSetAttribute(k_gemm3<QKVN, DIM / KSPLIT_QKV, false>,
                             cudaFuncAttributeMaxDynamicSharedMemorySize, QKV_SMEM);
        cudaFuncSetAttribute(k_gemm3<DIM, DIM / KSPLIT_WO, true>,
                             cudaFuncAttributeMaxDynamicSharedMemorySize, WO_SMEM);
        attr_done = 1;
    }

    k_gemm3<QKVN, DIM / KSPLIT_QKV, false>
        <<<dim3(QKVN / 256, KSPLIT_QKV), 128, QKV_SMEM>>>(x, wqkv);
    k_reduce_rope<<<(BATCH * 2560 + BATCH * 1024 + 255) / 256, 256>>>(sp);
    k_attn5<<<dim3(NCH, BATCH * NKV), 128, ATTN_SMEM>>>(ck, cv, sp);
    k_combine<<<BATCH * NKV, 128>>>();
    k_gemm3<DIM, DIM / KSPLIT_WO, true>
        <<<dim3(DIM / 256, KSPLIT_WO), 128, WO_SMEM>>>(nullptr, wo);
    k_wo_reduce<<<(BATCH * DIM) / 256, 256>>>(out);
}

// round 9
// speedup vs baseline: 1.8885x; 1.0358x over previous
#include <cuda_runtime.h>
#include <cuda_bf16.h>
#include <math.h>

#define BATCH   32
#define DIM     4096
#define NKV     8
#define REP     4
#define HD      128
#define QKVN    6144      // (32 + 2*8) * 128
#define CL      2176      // cache length
#define NCH     17        // 17 * 128 = 2176
#define KSPLIT_QKV  16
#define KSPLIT_WO   32

// ---------------- f32x2 packed-math helpers -----------------------------------
#define FFMA2(d, a, b, c) \
    asm("fma.rn.f32x2 %0, %1, %2, %3;" : "=l"(d) : "l"(a), "l"(b), "l"(c))
#define PACK2(d, s) \
    asm("mov.b64 %0, {%1, %1};" : "=l"(d) : "f"(s))
#define UNPACK2(lo, hi, v) \
    asm("mov.b64 {%0, %1}, %2;" : "=f"(lo), "=f"(hi) : "l"(v))
#define LDSV2(p01, p23, addr) \
    asm("ld.shared.v2.u64 {%0, %1}, [%2];" : "=l"(p01), "=l"(p23) : "r"(addr))

// ---------------- cp.async helpers ---------------------------------------------
#define CP_ASYNC16(dst_s, src_g) \
    asm volatile("cp.async.cg.shared.global [%0], [%1], 16;" \
                 :: "r"(dst_s), "l"(src_g) : "memory")
#define CP_COMMIT() asm volatile("cp.async.commit_group;" ::: "memory")
#define CP_WAIT(n)  asm volatile("cp.async.wait_group %0;" :: "n"(n) : "memory")

// ---------------- scratch (static device globals; no allocs allowed) ----------
__device__ float g_qkvp[KSPLIT_QKV * BATCH * QKVN];       // 12.6 MB
__device__ float g_q[BATCH * DIM];                        // (b, g, r, d)
__device__ float g_k[BATCH * NKV * HD];
__device__ float g_v[BATCH * NKV * HD];
__device__ float g_pacc[(size_t)BATCH * NKV * NCH * REP * HD];
__device__ float g_pm[BATCH * NKV * NCH * REP];
__device__ float g_pl[BATCH * NKV * NCH * REP];
__device__ float g_attn[BATCH * DIM];
__device__ float g_wop[KSPLIT_WO * BATCH * DIM];          // 16.8 MB

// ---------------- skinny GEMM v3: cp.async weight staging ----------------------
// out[32, N] partials over K-splits. grid(N/256, NSPLIT), 128 threads.
// Thread owns ADJACENT columns n0 = blk*256 + 2t, n1 = n0 + 1.
// x transposed in smem: xs_t[k][m], stride 36 floats (16B-aligned rows).
// Weights stream via cp.async in 16-row x 256-col chunks, double-buffered.
// NOTE: final chunk must use wait_group 0 (no younger group left to pend on).
template<int N, int KC, bool WO>
__global__ __launch_bounds__(128) void k_gemm3(const float* __restrict__ xsrc,
                                               const float* __restrict__ w) {
    extern __shared__ float smg[];
    float* xs_t = smg;                 // KC * 36 floats
    float* wt   = smg + KC * 36;       // 2 * 16 * 256 floats

    const int t    = threadIdx.x;
    const int k0   = blockIdx.y * KC;
    const int nblk = blockIdx.x * 256;
    constexpr int NCHW = KC / 16;      // weight chunks

    const float* xbase = WO ? (const float*)g_attn : xsrc;
    float*       obase = WO ? (float*)g_wop : (float*)g_qkvp;

    const unsigned wts = (unsigned)__cvta_generic_to_shared(wt);

    // issue weight chunk cb (16 rows x 256 cols = 16 KB) into buffer cb&1
    auto issue = [&](int cb) {
        const float* src = w + (size_t)(k0 + cb * 16) * N + nblk;
        unsigned dst = wts + (cb & 1) * 16384;
        #pragma unroll
        for (int it = 0; it < 8; it++) {
            int idx = t + 128 * it;            // 0..1023
            int row = idx >> 6;                // 64 x 16B per row
            int c16 = idx & 63;
            CP_ASYNC16(dst + (row * 256 + c16 * 4) * 4,
                       (const void*)(src + (size_t)row * N + c16 * 4));
        }
        CP_COMMIT();
    };
    issue(0);
    issue(1);

    // load + transpose x chunk: [32][KC] -> xs_t[k][m]
    const float4* xg = (const float4*)xbase;
    #pragma unroll
    for (int j = t; j < 8 * KC; j += 128) {
        int m  = j / (KC / 4);
        int c4 = j % (KC / 4);
        float4 v = xg[m * (DIM / 4) + (k0 >> 2) + c4];
        xs_t[(4 * c4 + 0) * 36 + m] = v.x;
        xs_t[(4 * c4 + 1) * 36 + m] = v.y;
        xs_t[(4 * c4 + 2) * 36 + m] = v.z;
        xs_t[(4 * c4 + 3) * 36 + m] = v.w;
    }

    const unsigned xa = (unsigned)__cvta_generic_to_shared(xs_t);

    unsigned long long acc0[16], acc1[16];
    #pragma unroll
    for (int mp = 0; mp < 16; mp++) { acc0[mp] = 0ull; acc1[mp] = 0ull; }

    for (int cb = 0; cb < NCHW; cb++) {
        if (cb + 1 < NCHW) { CP_WAIT(1); }      // chunk cb complete, cb+1 may fly
        else               { CP_WAIT(0); }      // FINAL chunk: full drain
        __syncthreads();               // chunk cb present (+ xs_t on cb==0)
        const float* wchunk = wt + (cb & 1) * 4096;
        #pragma unroll
        for (int kk = 0; kk < 16; kk++) {
            float2 wv = *(const float2*)&wchunk[kk * 256 + 2 * t];
            unsigned long long w0p, w1p;
            PACK2(w0p, wv.x);
            PACK2(w1p, wv.y);
            unsigned ra = xa + (cb * 16 + kk) * 144;
            #pragma unroll
            for (int j = 0; j < 8; j++) {
                unsigned long long x01, x23;
                LDSV2(x01, x23, ra + j * 16);
                FFMA2(acc0[2 * j],     x01, w0p, acc0[2 * j]);
                FFMA2(acc0[2 * j + 1], x23, w0p, acc0[2 * j + 1]);
                FFMA2(acc1[2 * j],     x01, w1p, acc1[2 * j]);
                FFMA2(acc1[2 * j + 1], x23, w1p, acc1[2 * j + 1]);
            }
        }
        __syncthreads();               // all reads of buffer cb&1 done
        if (cb + 2 < NCHW) issue(cb + 2);
    }

    // epilogue: row m gets columns (2t, 2t+1) -> one float2 store per row
    float* o = obase + (size_t)blockIdx.y * 32 * N + nblk + 2 * t;
    #pragma unroll
    for (int mp = 0; mp < 16; mp++) {
        float a0, b0, a1, b1;
        UNPACK2(a0, b0, acc0[mp]);
        UNPACK2(a1, b1, acc1[mp]);
        float2 lo = make_float2(a0, a1);
        float2 hi = make_float2(b0, b1);
        *(float2*)&o[(size_t)(2 * mp) * N]     = lo;
        *(float2*)&o[(size_t)(2 * mp + 1) * N] = hi;
    }
}

// ---------------- reduce QKV K-split partials + RoPE (pairwise, fused table) ---
__global__ __launch_bounds__(256) void k_reduce_rope(const int* __restrict__ spp) {
    __shared__ float cs[64], sn[64];
    int tt = threadIdx.x;
    if (tt < 64) {
        int sp = *spp;
        double e    = (2.0 * (double)tt) / 128.0;
        double invf = pow(10000.0, -e);
        double ang  = (double)sp * invf;
        cs[tt] = (float)cos(ang);
        sn[tt] = (float)sin(ang);
    }
    __syncthreads();

    int idx = blockIdx.x * 256 + tt;

    if (idx < BATCH * 2560) {
        int m = idx / 2560;
        int p = idx % 2560;
        int h = p >> 6;                                  // head 0..39 (q then k)
        int i = p & 63;                                  // low dim
        int n  = h * 128 + i;
        int n2 = n + 64;

        float s = 0.f, s2 = 0.f;
        #pragma unroll
        for (int sp = 0; sp < KSPLIT_QKV; sp++) {
            const float* base = g_qkvp + ((size_t)sp * BATCH + m) * QKVN;
            s  += base[n];
            s2 += base[n2];
        }
        float co = cs[i], si = sn[i];
        float out1 = s * co - s2 * si;
        float out2 = s2 * co + s * si;
        if (n < 4096) {
            g_q[m * DIM + n]  = out1;
            g_q[m * DIM + n2] = out2;
        } else {
            g_k[m * (NKV * HD) + (n - 4096)]  = out1;
            g_k[m * (NKV * HD) + (n2 - 4096)] = out2;
        }
    } else if (idx < BATCH * 2560 + BATCH * 1024) {
        int j = idx - BATCH * 2560;
        int m = j >> 10;
        int n = 5120 + (j & 1023);
        float s = 0.f;
        #pragma unroll
        for (int sp = 0; sp < KSPLIT_QKV; sp++)
            s += g_qkvp[((size_t)sp * BATCH + m) * QKVN + n];
        g_v[m * (NKV * HD) + (n - 5120)] = s;
    }
}

// ---------------- flash-decode attention v5: per-warp decoupled pipeline -------
__global__ __launch_bounds__(128) void k_attn5(const float* __restrict__ ck,
                                               const float* __restrict__ cv,
                                               const int* __restrict__ spp) {
    extern __shared__ float sm[];
    float* qp  = sm;                  // 512 : q packed [d][4 reps]
    float* ps  = sm + 512;            // 512 : scores/probs [s][4 reps]
    float* red = sm + 1024;           // 16  : m[0..3], l[4..7]
    float* kvs = sm + 1040;           // 16896 = 128*132 (K tile, then V tile)

    const int t  = threadIdx.x;
    const int w  = t >> 5;
    const int l  = t & 31;
    const int c  = blockIdx.x;
    const int bg = blockIdx.y;
    const int sp = *spp;
    const float SCALE = 0.08838834764831845f;            // 1/sqrt(128)

    const float4* ckb = ((const float4*)ck) + (size_t)bg * CL * 32;
    const float4* cvb = ((const float4*)cv) + (size_t)bg * CL * 32;
    const float4* gk4 = ((const float4*)g_k) + bg * 32;
    const float4* gv4 = ((const float4*)g_v) + bg * 32;

    const unsigned qa   = (unsigned)__cvta_generic_to_shared(qp);
    const unsigned psa  = (unsigned)__cvta_generic_to_shared(ps);
    const unsigned kvsa = (unsigned)__cvta_generic_to_shared(kvs);

    const int s0  = c * 128;
    const int rw0 = w * 32;           // this warp's first row

    // ---- warp w issues K for its 32 rows ----
    #pragma unroll
    for (int it = 0; it < 32; it++) {
        int j   = l + 32 * it;
        int row = rw0 + (j >> 5);
        int c4  = j & 31;
        CP_ASYNC16(kvsa + row * 528 + c4 * 16,
                   (const void*)&ckb[(s0 + row) * 32 + c4]);
    }
    CP_COMMIT();

    // q packed: qp[d*4 + r] (all threads)
    #pragma unroll
    for (int it = 0; it < 4; it++) {
        int idx = t + 128 * it;
        int d = idx & 127, r = idx >> 7;
        qp[d * 4 + r] = g_q[(size_t)bg * 512 + r * 128 + d];
    }
    __syncthreads();                  // qp visible (K loads still in flight)

    // ---- per-warp: wait own K, patch new-token row, score own rows ----
    CP_WAIT(0);
    __syncwarp();
    if (sp >= s0 + rw0 && sp < s0 + rw0 + 32)
        ((float4*)(kvs + (sp - s0) * 132))[l] = gk4[l];
    __syncwarp();
    {
        const int rloc = rw0 + l;
        const float4* kr = ((const float4*)kvs) + rloc * 33;
        unsigned long long a01 = 0ull, a23 = 0ull;
        #pragma unroll 8
        for (int d4 = 0; d4 < 32; d4++) {
            float4 kv = kr[d4];
            unsigned qd = qa + d4 * 64;
            unsigned long long kp, q01, q23;
            PACK2(kp, kv.x); LDSV2(q01, q23, qd +  0);
            FFMA2(a01, kp, q01, a01); FFMA2(a23, kp, q23, a23);
            PACK2(kp, kv.y); LDSV2(q01, q23, qd + 16);
            FFMA2(a01, kp, q01, a01); FFMA2(a23, kp, q23, a23);
            PACK2(kp, kv.z); LDSV2(q01, q23, qd + 32);
            FFMA2(a01, kp, q01, a01); FFMA2(a23, kp, q23, a23);
            PACK2(kp, kv.w); LDSV2(q01, q23, qd + 48);
            FFMA2(a01, kp, q01, a01); FFMA2(a23, kp, q23, a23);
        }
        float v0, v1, v2, v3;
        UNPACK2(v0, v1, a01); UNPACK2(v2, v3, a23);
        int  sg = s0 + rloc;
        bool ok = (sg <= sp);
        float4 sv;
        sv.x = ok ? v0 * SCALE : -1e9f;
        sv.y = ok ? v1 * SCALE : -1e9f;
        sv.z = ok ? v2 * SCALE : -1e9f;
        sv.w = ok ? v3 * SCALE : -1e9f;
        ((float4*)ps)[rloc] = sv;
    }

    // ---- immediately issue V for own rows (overwrites own K region) ----
    #pragma unroll
    for (int it = 0; it < 32; it++) {
        int j   = l + 32 * it;
        int row = rw0 + (j >> 5);
        int c4  = j & 31;
        CP_ASYNC16(kvsa + row * 528 + c4 * 16,
                   (const void*)&cvb[(s0 + row) * 32 + c4]);
    }
    CP_COMMIT();

    __syncthreads();                  // all scores in ps

    // ---- softmax over this chunk: warp w handles rep r = w ----
    {
        float v0 = ps[(l +  0) * 4 + w];
        float v1 = ps[(l + 32) * 4 + w];
        float v2 = ps[(l + 64) * 4 + w];
        float v3 = ps[(l + 96) * 4 + w];
        float mx = fmaxf(fmaxf(v0, v1), fmaxf(v2, v3));
        #pragma unroll
        for (int off = 16; off > 0; off >>= 1)
            mx = fmaxf(mx, __shfl_xor_sync(0xffffffffu, mx, off));
        float e0 = expf(v0 - mx), e1 = expf(v1 - mx);
        float e2 = expf(v2 - mx), e3 = expf(v3 - mx);
        float sum = e0 + e1 + e2 + e3;
        #pragma unroll
        for (int off = 16; off > 0; off >>= 1)
            sum += __shfl_xor_sync(0xffffffffu, sum, off);
        ps[(l +  0) * 4 + w] = e0;
        ps[(l + 32) * 4 + w] = e1;
        ps[(l + 64) * 4 + w] = e2;
        ps[(l + 96) * 4 + w] = e3;
        if (l == 0) { red[w] = mx; red[4 + w] = sum; }
    }

    // ---- wait own V, patch own-range new-token V row ----
    CP_WAIT(0);
    __syncwarp();
    if (sp >= s0 + rw0 && sp < s0 + rw0 + 32)
        ((float4*)(kvs + (sp - s0) * 132))[l] = gv4[l];
    __syncthreads();                  // all V rows + all probs visible

    // ---- PV: thread t owns head dim d = t, full 128 rows ----
    unsigned long long o01 = 0ull, o23 = 0ull;
    #pragma unroll 8
    for (int s = 0; s < 128; s++) {
        float vv = kvs[s * 132 + t];
        unsigned long long vp, p01, p23;
        PACK2(vp, vv);
        LDSV2(p01, p23, psa + s * 16);
        FFMA2(o01, vp, p01, o01);
        FFMA2(o23, vp, p23, o23);
    }

    float o0, o1, o2, o3;
    UNPACK2(o0, o1, o01);
    UNPACK2(o2, o3, o23);
    size_t pb = ((size_t)bg * NCH + c) * REP;
    g_pacc[(pb + 0) * HD + t] = o0;
    g_pacc[(pb + 1) * HD + t] = o1;
    g_pacc[(pb + 2) * HD + t] = o2;
    g_pacc[(pb + 3) * HD + t] = o3;
    if (t < REP) { g_pm[pb + t] = red[t]; g_pl[pb + t] = red[4 + t]; }
}

// ---------------- combine split-S partials v2: 512 threads, weights in smem ----
// Block bg. Threads 0..3 compute per-(chunk, rep) softmax-combine weights and
// 1/L into smem; then thread (r = t>>7, d = t&127) does 17 INDEPENDENT g_pacc
// loads + FMAs. 4x parallelism of v1 and no expf in the hot path.
__global__ __launch_bounds__(512) void k_combine2() {
    __shared__ float wgt[NCH * REP];
    __shared__ float invL[REP];
    const int bg = blockIdx.x;
    const int t  = threadIdx.x;

    if (t < REP) {
        float M = -1e30f;
        float ms[NCH];
        #pragma unroll
        for (int cc = 0; cc < NCH; cc++) {
            ms[cc] = g_pm[(bg * NCH + cc) * REP + t];
            M = fmaxf(M, ms[cc]);
        }
        float L = 0.f;
        #pragma unroll
        for (int cc = 0; cc < NCH; cc++) {
            float wg = expf(ms[cc] - M);
            wgt[cc * REP + t] = wg;
            L += g_pl[(bg * NCH + cc) * REP + t] * wg;
        }
        invL[t] = 1.f / L;
    }
    __syncthreads();

    const int r = t >> 7;
    const int d = t & 127;
    const float* pa = g_pacc + ((size_t)bg * NCH * REP + r) * HD + d;
    float val = 0.f;
    #pragma unroll
    for (int cc = 0; cc < NCH; cc++)
        val += pa[(size_t)cc * REP * HD] * wgt[cc * REP + r];
    g_attn[(size_t)bg * 512 + r * HD + d] = val * invL[r];
}

// ---------------- WO split-K reduce --------------------------------------------
__global__ __launch_bounds__(256) void k_wo_reduce(float* __restrict__ out) {
    int idx = blockIdx.x * 256 + threadIdx.x;            // < 32*4096
    float s = 0.f;
    #pragma unroll
    for (int p = 0; p < KSPLIT_WO; p++) s += g_wop[(size_t)p * BATCH * DIM + idx];
    out[idx] = s;
}

// ---------------- launch -------------------------------------------------------
extern "C" void kernel_launch(void* const* d_in, const int* in_sizes, int n_in,
                              void* d_out, int out_size) {
    const float* x    = (const float*)d_in[0];
    const float* wqkv = (const float*)d_in[1];
    const float* wo   = (const float*)d_in[2];
    const float* ck   = (const float*)d_in[3];
    const float* cv   = (const float*)d_in[4];
    const int*   sp   = (const int*)d_in[5];
    float*       out  = (float*)d_out;

    const int ATTN_SMEM = (512 + 512 + 16 + 16896) * 4;            // 71744 B
    const int QKV_SMEM  = ((DIM / KSPLIT_QKV) * 36 + 8192) * 4;    // 69632 B
    const int WO_SMEM   = ((DIM / KSPLIT_WO) * 36 + 8192) * 4;     // 51200 B
    static int attr_done = 0;
    if (!attr_done) {
        cudaFuncSetAttribute(k_attn5, cudaFuncAttributeMaxDynamicSharedMemorySize,
                             ATTN_SMEM);
        cudaFuncSetAttribute(k_gemm3<QKVN, DIM / KSPLIT_QKV, false>,
                             cudaFuncAttributeMaxDynamicSharedMemorySize, QKV_SMEM);
        cudaFuncSetAttribute(k_gemm3<DIM, DIM / KSPLIT_WO, true>,
                             cudaFuncAttributeMaxDynamicSharedMemorySize, WO_SMEM);
        attr_done = 1;
    }

    k_gemm3<QKVN, DIM / KSPLIT_QKV, false>
        <<<dim3(QKVN / 256, KSPLIT_QKV), 128, QKV_SMEM>>>(x, wqkv);
    k_reduce_rope<<<(BATCH * 2560 + BATCH * 1024 + 255) / 256, 256>>>(sp);
    k_attn5<<<dim3(NCH, BATCH * NKV), 128, ATTN_SMEM>>>(ck, cv, sp);
    k_combine2<<<BATCH * NKV, 512>>>();
    k_gemm3<DIM, DIM / KSPLIT_WO, true>
        <<<dim3(DIM / 256, KSPLIT_WO), 128, WO_SMEM>>>(nullptr, wo);
    k_wo_reduce<<<(BATCH * DIM) / 256, 256>>>(out);
}